// round 10
// baseline (speedup 1.0000x reference)
#include <cuda_runtime.h>
#include <cuda_bf16.h>
#include <math.h>
#include <stdint.h>

// ---------------------------------------------------------------------------
// Problem constants (B=4, N=2048, D=2048, H=16, DK=128, R=32)
// ---------------------------------------------------------------------------
#define B_   4
#define N_   2048
#define D_   2048
#define H_   16
#define DK_  128
#define R_   32
#define M_   (B_ * N_)      // 8192
#define HR_  (H_ * R_)      // 512

// ---------------------------------------------------------------------------
// Device scratch (bf16 hi/lo everywhere between stages)
// ---------------------------------------------------------------------------
__device__ __nv_bfloat16 g_xh [(size_t)M_ * D_];
__device__ __nv_bfloat16 g_xl [(size_t)M_ * D_];
__device__ __nv_bfloat16 g_WUqh[(size_t)HR_ * D_];
__device__ __nv_bfloat16 g_WUql[(size_t)HR_ * D_];
__device__ __nv_bfloat16 g_WUkh[(size_t)HR_ * D_];
__device__ __nv_bfloat16 g_WUkl[(size_t)HR_ * D_];
__device__ __nv_bfloat16 g_Wvh[(size_t)D_ * D_];
__device__ __nv_bfloat16 g_Wvl[(size_t)D_ * D_];
__device__ __nv_bfloat16 g_Wph[(size_t)D_ * D_];
__device__ __nv_bfloat16 g_Wpl[(size_t)D_ * D_];
__device__ __nv_bfloat16 g_Qh[(size_t)B_ * H_ * N_ * R_];
__device__ __nv_bfloat16 g_Ql[(size_t)B_ * H_ * N_ * R_];
__device__ __nv_bfloat16 g_Kh[(size_t)B_ * H_ * N_ * R_];
__device__ __nv_bfloat16 g_Kl[(size_t)B_ * H_ * N_ * R_];
__device__ __nv_bfloat16 g_Vh[(size_t)B_ * H_ * N_ * DK_];
__device__ __nv_bfloat16 g_Vl[(size_t)B_ * H_ * N_ * DK_];
__device__ __nv_bfloat16 g_Zh[(size_t)M_ * D_];
__device__ __nv_bfloat16 g_Zl[(size_t)M_ * D_];

// ---------------------------------------------------------------------------
// PTX wrappers (sm_80-era, valid on plain sm_103 target)
// ---------------------------------------------------------------------------
__device__ __forceinline__ uint32_t smem_u32(const void* p) {
    uint32_t a;
    asm("{ .reg .u64 t; cvta.to.shared.u64 t, %1; cvt.u32.u64 %0, t; }"
        : "=r"(a) : "l"(p));
    return a;
}
__device__ __forceinline__ void ldsm_x4(uint32_t* r, uint32_t addr) {
    asm volatile("ldmatrix.sync.aligned.m8n8.x4.shared.b16 {%0,%1,%2,%3}, [%4];"
                 : "=r"(r[0]), "=r"(r[1]), "=r"(r[2]), "=r"(r[3]) : "r"(addr));
}
__device__ __forceinline__ void ldsm_x2(uint32_t* r, uint32_t addr) {
    asm volatile("ldmatrix.sync.aligned.m8n8.x2.shared.b16 {%0,%1}, [%2];"
                 : "=r"(r[0]), "=r"(r[1]) : "r"(addr));
}
__device__ __forceinline__ void ldsm_x4_t(uint32_t* r, uint32_t addr) {
    asm volatile("ldmatrix.sync.aligned.m8n8.x4.trans.shared.b16 {%0,%1,%2,%3}, [%4];"
                 : "=r"(r[0]), "=r"(r[1]), "=r"(r[2]), "=r"(r[3]) : "r"(addr));
}
__device__ __forceinline__ void mma_bf16(float* d, const uint32_t* a, const uint32_t* b) {
    asm volatile(
        "mma.sync.aligned.m16n8k16.row.col.f32.bf16.bf16.f32 "
        "{%0,%1,%2,%3}, {%4,%5,%6,%7}, {%8,%9}, {%0,%1,%2,%3};"
        : "+f"(d[0]), "+f"(d[1]), "+f"(d[2]), "+f"(d[3])
        : "r"(a[0]), "r"(a[1]), "r"(a[2]), "r"(a[3]), "r"(b[0]), "r"(b[1]));
}
__device__ __forceinline__ void cp16(uint32_t dst, const void* src) {
    asm volatile("cp.async.cg.shared.global [%0], [%1], 16;"
                 :: "r"(dst), "l"(src) : "memory");
}
#define CP_COMMIT() asm volatile("cp.async.commit_group;" ::: "memory")
#define CP_WAIT1()  asm volatile("cp.async.wait_group 1;" ::: "memory")
#define CP_WAIT2()  asm volatile("cp.async.wait_group 2;" ::: "memory")

__device__ __forceinline__ void split2(float x, __nv_bfloat16& h, __nv_bfloat16& l) {
    h = __float2bfloat16(x);
    l = __float2bfloat16(x - __bfloat162float(h));
}
__device__ __forceinline__ uint32_t packbf(__nv_bfloat16 a, __nv_bfloat16 b) {
    return (uint32_t)__bfloat16_as_ushort(a) | ((uint32_t)__bfloat16_as_ushort(b) << 16);
}
__device__ __forceinline__ void pack_hilo(float x, float y, uint32_t& hi, uint32_t& lo) {
    __nv_bfloat16 hx, lx, hy, ly;
    split2(x, hx, lx); split2(y, hy, ly);
    hi = packbf(hx, hy); lo = packbf(lx, ly);
}

// ---------------------------------------------------------------------------
// Prep kernels
// ---------------------------------------------------------------------------
__global__ void split_bf16_kernel(const float4* __restrict__ in,
                                  uint2* __restrict__ hi, uint2* __restrict__ lo, int n4)
{
    int i = blockIdx.x * 256 + threadIdx.x;
    if (i >= n4) return;
    float4 v = in[i];
    __nv_bfloat16 h0, h1, h2, h3, l0, l1, l2, l3;
    split2(v.x, h0, l0); split2(v.y, h1, l1);
    split2(v.z, h2, l2); split2(v.w, h3, l3);
    hi[i] = make_uint2(packbf(h0, h1), packbf(h2, h3));
    lo[i] = make_uint2(packbf(l0, l1), packbf(l2, l3));
}

// WU[h*32 + r, d] = sum_dk W[h*128+dk, d] * U[dk, r]; each thread does 8 r's.
// grid (D/256, H, 4), block 256. U slice staged in smem.
__global__ void build_wu_kernel(const float* __restrict__ W,
                                const float* __restrict__ U,
                                __nv_bfloat16* __restrict__ WUh,
                                __nv_bfloat16* __restrict__ WUl)
{
    __shared__ float Us[128][8];
    const int tid = threadIdx.x;
    const int d   = blockIdx.x * 256 + tid;
    const int h   = blockIdx.y;
    const int rg  = blockIdx.z;          // r group: rows rg*8 .. rg*8+7

    for (int i = tid; i < 128 * 8; i += 256) {
        int dk = i >> 3, j = i & 7;
        Us[dk][j] = U[dk * R_ + rg * 8 + j];
    }
    __syncthreads();

    const float* wcol = W + (size_t)h * DK_ * D_ + d;
    float acc[8];
#pragma unroll
    for (int j = 0; j < 8; j++) acc[j] = 0.f;
#pragma unroll 4
    for (int dk = 0; dk < DK_; dk++) {
        float w = wcol[(size_t)dk * D_];
#pragma unroll
        for (int j = 0; j < 8; j++) acc[j] = fmaf(w, Us[dk][j], acc[j]);
    }
#pragma unroll
    for (int j = 0; j < 8; j++) {
        __nv_bfloat16 hh, ll;
        split2(acc[j], hh, ll);
        size_t off = (size_t)(h * 32 + rg * 8 + j) * D_ + d;
        WUh[off] = hh;
        WUl[off] = ll;
    }
}

// ---------------------------------------------------------------------------
// HMMA 3xBF16 GEMM v3: CTA 128(M) x 256(N), BK=32, 8 warps as 2(M) x 4(N),
// warp tile 64x64 (MMA/ldmatrix-wf ratio 1.5 -> tensor-bound).
// smem/stage: AH|AL 128x80B @0/10240, BH|BL 256x80B @20480/40960 = 61440 B.
// 2 stages = 122880 B, 1 CTA/SM.
// MODE 0: fp32 C[m*NN+n]
// MODE 1: bf16 hi/lo head-split (scaled): off = ((b*H + n/SPLIT)*N + m%N)*SPLIT + n%SPLIT
// ---------------------------------------------------------------------------
#define SG_SIZE 61440
#define GEMM_SMEM (2 * SG_SIZE)

template <int MODE, int SPLIT>
__global__ void __launch_bounds__(256)
gemm_cp_bf16x3(const __nv_bfloat16* __restrict__ Ah,
               const __nv_bfloat16* __restrict__ Al,
               const __nv_bfloat16* __restrict__ Bh,
               const __nv_bfloat16* __restrict__ Bl,
               float* __restrict__ Cf,
               __nv_bfloat16* __restrict__ Ch,
               __nv_bfloat16* __restrict__ Cl,
               int NN, int K, float scale)
{
    extern __shared__ char sm[];
    const uint32_t sb = smem_u32(sm);

    const int tid  = threadIdx.x;
    const int lane = tid & 31;
    const int wid  = tid >> 5;
    const int wm   = wid & 1;      // 0..1 : 64 M-rows
    const int wn   = wid >> 1;     // 0..3 : 64 N-cols
    const int m0   = blockIdx.y * 128;
    const int n0   = blockIdx.x * 256;

    // issue cp.async loads for K-iteration `it` into stage `st`
    auto issue = [&](int st, int it) {
        const uint32_t stb = sb + (uint32_t)st * SG_SIZE;
        // A: 1024 16B chunks (hi 512 + lo 512)
#pragma unroll
        for (int v = 0; v < 4; v++) {
            int idx  = v * 256 + tid;          // 0..1023
            int part = idx >> 9;               // 0 hi, 1 lo
            int r    = (idx & 511) >> 2;       // 0..127
            int q    = idx & 3;
            const __nv_bfloat16* src =
                (part ? Al : Ah) + (size_t)(m0 + r) * K + it * 32 + q * 8;
            cp16(stb + part * 10240 + (uint32_t)(r * 80 + q * 16), src);
        }
        // B: 2048 16B chunks (hi 1024 + lo 1024)
#pragma unroll
        for (int v = 0; v < 8; v++) {
            int idx  = v * 256 + tid;          // 0..2047
            int part = idx >> 10;
            int r    = (idx & 1023) >> 2;      // 0..255
            int q    = idx & 3;
            const __nv_bfloat16* src =
                (part ? Bl : Bh) + (size_t)(n0 + r) * K + it * 32 + q * 8;
            cp16(stb + 20480 + part * 20480 + (uint32_t)(r * 80 + q * 16), src);
        }
    };

    const int niter = K / 32;
    issue(0, 0); CP_COMMIT();
    issue(1, 1); CP_COMMIT();

    float acc[4][8][4];
#pragma unroll
    for (int mi = 0; mi < 4; mi++)
#pragma unroll
        for (int ni = 0; ni < 8; ni++)
#pragma unroll
            for (int f = 0; f < 4; f++) acc[mi][ni][f] = 0.f;

    const uint32_t a_off =
        (uint32_t)((wm * 64 + (lane & 15)) * 80 + (lane >> 4) * 16);
    const uint32_t b_off = 20480u +
        (uint32_t)((wn * 64 + (lane & 7)) * 80 + ((lane >> 3) & 1) * 16);

    for (int it = 0; it < niter; ++it) {
        CP_WAIT1();
        __syncthreads();
        const uint32_t stb = sb + (uint32_t)(it & 1) * SG_SIZE;
        const uint32_t a_addr = stb + a_off;
        const uint32_t b_addr = stb + b_off;

#pragma unroll
        for (int ks = 0; ks < 2; ks++) {
            uint32_t ah[4][4], al[4][4];
#pragma unroll
            for (int mi = 0; mi < 4; mi++) {
                uint32_t off = (uint32_t)(mi * 1280 + ks * 32);
                ldsm_x4(ah[mi], a_addr + off);
                ldsm_x4(al[mi], a_addr + off + 10240);
            }
#pragma unroll
            for (int ni = 0; ni < 8; ni++) {
                uint32_t bh[2], bl[2];
                uint32_t off = (uint32_t)(ni * 640 + ks * 32);
                ldsm_x2(bh, b_addr + off);
                ldsm_x2(bl, b_addr + off + 20480);
#pragma unroll
                for (int mi = 0; mi < 4; mi++) {
                    mma_bf16(acc[mi][ni], ah[mi], bh);
                    mma_bf16(acc[mi][ni], ah[mi], bl);
                    mma_bf16(acc[mi][ni], al[mi], bh);
                }
            }
        }
        __syncthreads();
        if (it + 2 < niter) { issue(it & 1, it + 2); CP_COMMIT(); }
    }

    // epilogue
    const int g  = lane >> 2;
    const int c2 = (lane & 3) * 2;
#pragma unroll
    for (int mi = 0; mi < 4; mi++) {
#pragma unroll
        for (int ni = 0; ni < 8; ni++) {
            int m = m0 + wm * 64 + mi * 16 + g;
            int n = n0 + wn * 64 + ni * 8 + c2;
#pragma unroll
            for (int half = 0; half < 2; half++) {
                int mm = m + half * 8;
                float v0 = acc[mi][ni][half * 2];
                float v1 = acc[mi][ni][half * 2 + 1];
                if (MODE == 0) {
                    *(float2*)(Cf + (size_t)mm * NN + n) = make_float2(v0, v1);
                } else {
                    int b_ = mm >> 11;
                    int t  = mm & (N_ - 1);
                    int h  = n / SPLIT;
                    int j  = n % SPLIT;
                    size_t off = (((size_t)(b_ * H_ + h)) * N_ + t) * SPLIT + j;
                    uint32_t hi, lo;
                    pack_hilo(v0 * scale, v1 * scale, hi, lo);
                    *(uint32_t*)(Ch + off) = hi;
                    *(uint32_t*)(Cl + off) = lo;
                }
            }
        }
    }
}

// ---------------------------------------------------------------------------
// HMMA flash attention (unchanged from R9; proven, rel_err 2.2e-5)
// ---------------------------------------------------------------------------
#define FQ_H 0
#define FQ_L 10240
#define FK_BASE 20480
#define FK_STAGE 20480
#define FV_BASE 61440
#define FV_STAGE 69632
#define FLM_SMEM 200704
#define VSTR 272

__global__ void __launch_bounds__(256, 1)
flash_cp_kernel(const __nv_bfloat16* __restrict__ Qh, const __nv_bfloat16* __restrict__ Ql,
                const __nv_bfloat16* __restrict__ Kh, const __nv_bfloat16* __restrict__ Kl,
                const __nv_bfloat16* __restrict__ Vh, const __nv_bfloat16* __restrict__ Vl,
                __nv_bfloat16* __restrict__ Zh, __nv_bfloat16* __restrict__ Zl)
{
    extern __shared__ char sm[];
    const uint32_t sb = smem_u32(sm);

    const int tid  = threadIdx.x;
    const int lane = tid & 31;
    const int wq   = tid >> 5;
    const int bh   = blockIdx.y;
    const int h    = bh & (H_ - 1);
    const int b_   = bh >> 4;
    const int q0   = blockIdx.x * 128;
    const int g    = lane >> 2;
    const int t4   = lane & 3;

    const float slope = exp2f(-0.5f * (float)(h + 1));
    const float NEG_INF = -__int_as_float(0x7f800000);

    auto issue_kv = [&](int st, int kt2) {
        const int k0 = kt2 * 128;
        const __nv_bfloat16* kh = Kh + ((size_t)bh * N_ + k0) * R_;
        const __nv_bfloat16* kl = Kl + ((size_t)bh * N_ + k0) * R_;
#pragma unroll
        for (int v = 0; v < 4; v++) {
            int idx = (v & 1) * 256 + tid;
            int row = idx >> 2, q = idx & 3;
            const __nv_bfloat16* src = (v < 2 ? kh : kl) + (size_t)row * R_ + q * 8;
            uint32_t dst = sb + FK_BASE + st * FK_STAGE + (v < 2 ? 0 : 10240)
                         + (uint32_t)(row * 80 + q * 16);
            cp16(dst, src);
        }
        const __nv_bfloat16* vh = Vh + ((size_t)bh * N_ + k0) * DK_;
        const __nv_bfloat16* vl = Vl + ((size_t)bh * N_ + k0) * DK_;
#pragma unroll
        for (int v = 0; v < 16; v++) {
            int idx = (v & 7) * 256 + tid;
            int row = idx >> 4, q = idx & 15;
            const __nv_bfloat16* src = (v < 8 ? vh : vl) + (size_t)row * DK_ + q * 8;
            uint32_t dst = sb + FV_BASE + st * FV_STAGE + (v < 8 ? 0 : 34816)
                         + (uint32_t)(row * VSTR + q * 16);
            cp16(dst, src);
        }
    };

    {
        const __nv_bfloat16* qh_ = Qh + ((size_t)bh * N_ + q0) * R_;
        const __nv_bfloat16* ql_ = Ql + ((size_t)bh * N_ + q0) * R_;
#pragma unroll
        for (int v = 0; v < 4; v++) {
            int idx = (v & 1) * 256 + tid;
            int row = idx >> 2, q = idx & 3;
            const __nv_bfloat16* src = (v < 2 ? qh_ : ql_) + (size_t)row * R_ + q * 8;
            uint32_t dst = sb + (v < 2 ? FQ_H : FQ_L) + (uint32_t)(row * 80 + q * 16);
            cp16(dst, src);
        }
    }
    CP_COMMIT();
    issue_kv(0, 0); CP_COMMIT();
    issue_kv(1, 1); CP_COMMIT();

    CP_WAIT2();
    __syncthreads();

    uint32_t qh[2][4], ql[2][4];
    {
        uint32_t qaddr = sb + FQ_H +
            (uint32_t)((wq * 16 + (lane & 15)) * 40 + (lane >> 4) * 8) * 2;
#pragma unroll
        for (int ks = 0; ks < 2; ks++) {
            ldsm_x4(qh[ks], qaddr + ks * 32);
            ldsm_x4(ql[ks], qaddr + ks * 32 + 10240);
        }
    }

    float o[16][4];
#pragma unroll
    for (int d = 0; d < 16; d++)
#pragma unroll
        for (int f = 0; f < 4; f++) o[d][f] = 0.f;
    float m_i[2] = {NEG_INF, NEG_INF};
    float l_i[2] = {0.f, 0.f};

    for (int kt = 0; kt < N_ / 128; kt++) {
        const int k0 = kt * 128;
        CP_WAIT1();
        __syncthreads();
        const int st = kt & 1;

        float s[16][4];
#pragma unroll
        for (int nb = 0; nb < 16; nb++)
#pragma unroll
            for (int f = 0; f < 4; f++) s[nb][f] = 0.f;

        {
            uint32_t baddr = sb + FK_BASE + st * FK_STAGE +
                (uint32_t)((lane & 7) * 40 + ((lane >> 3) & 1) * 8) * 2;
#pragma unroll
            for (int ks = 0; ks < 2; ks++) {
#pragma unroll
                for (int nb = 0; nb < 16; nb++) {
                    uint32_t bhh[2], bll[2];
                    uint32_t off = (uint32_t)(nb * 640 + ks * 32);
                    ldsm_x2(bhh, baddr + off);
                    ldsm_x2(bll, baddr + off + 10240);
                    mma_bf16(s[nb], qh[ks], bhh);
                    mma_bf16(s[nb], qh[ks], bll);
                    mma_bf16(s[nb], ql[ks], bhh);
                }
            }
        }

#pragma unroll
        for (int nb = 0; nb < 16; nb++) {
#pragma unroll
            for (int f = 0; f < 4; f++) {
                int r = f >> 1, c = f & 1;
                int jg = k0 + nb * 8 + t4 * 2 + c;
                int ig = q0 + wq * 16 + g + r * 8;
                s[nb][f] -= slope * fmaxf((float)(jg - ig), 0.f);
            }
        }

        float alpha[2], mnew[2];
#pragma unroll
        for (int r = 0; r < 2; r++) {
            float tm = NEG_INF;
#pragma unroll
            for (int nb = 0; nb < 16; nb++) {
                tm = fmaxf(tm, s[nb][r * 2]);
                tm = fmaxf(tm, s[nb][r * 2 + 1]);
            }
            tm = fmaxf(tm, __shfl_xor_sync(0xffffffffu, tm, 1));
            tm = fmaxf(tm, __shfl_xor_sync(0xffffffffu, tm, 2));
            mnew[r]  = fmaxf(m_i[r], tm);
            alpha[r] = __expf(m_i[r] - mnew[r]);
            m_i[r]   = mnew[r];
        }

        float rsum[2] = {0.f, 0.f};
#pragma unroll
        for (int nb = 0; nb < 16; nb++) {
#pragma unroll
            for (int f = 0; f < 4; f++) {
                int r = f >> 1;
                float p = __expf(s[nb][f] - mnew[r]);
                s[nb][f] = p;
                rsum[r] += p;
            }
        }
#pragma unroll
        for (int r = 0; r < 2; r++) {
            rsum[r] += __shfl_xor_sync(0xffffffffu, rsum[r], 1);
            rsum[r] += __shfl_xor_sync(0xffffffffu, rsum[r], 2);
            l_i[r] = l_i[r] * alpha[r] + rsum[r];
        }
#pragma unroll
        for (int d = 0; d < 16; d++)
#pragma unroll
            for (int f = 0; f < 4; f++) o[d][f] *= alpha[f >> 1];

        {
            uint32_t vaddr = sb + FV_BASE + st * FV_STAGE +
                (uint32_t)((lane & 15) * VSTR + (lane >> 4) * 16);
#pragma unroll
            for (int ks = 0; ks < 8; ks++) {
                uint32_t aH[4], aL[4];
                pack_hilo(s[2 * ks][0],     s[2 * ks][1],     aH[0], aL[0]);
                pack_hilo(s[2 * ks][2],     s[2 * ks][3],     aH[1], aL[1]);
                pack_hilo(s[2 * ks + 1][0], s[2 * ks + 1][1], aH[2], aL[2]);
                pack_hilo(s[2 * ks + 1][2], s[2 * ks + 1][3], aH[3], aL[3]);
#pragma unroll
                for (int db = 0; db < 8; db++) {
                    uint32_t vh4[4], vl4[4];
                    uint32_t off = (uint32_t)(ks * 16 * VSTR + db * 32);
                    ldsm_x4_t(vh4, vaddr + off);
                    ldsm_x4_t(vl4, vaddr + off + 34816);
                    mma_bf16(o[db * 2],     aH, vh4);
                    mma_bf16(o[db * 2],     aH, vl4);
                    mma_bf16(o[db * 2],     aL, vh4);
                    mma_bf16(o[db * 2 + 1], aH, vh4 + 2);
                    mma_bf16(o[db * 2 + 1], aH, vl4 + 2);
                    mma_bf16(o[db * 2 + 1], aL, vh4 + 2);
                }
            }
        }
        __syncthreads();
        if (kt + 2 < N_ / 128) { issue_kv(st, kt + 2); CP_COMMIT(); }
    }

    float inv[2] = {1.f / l_i[0], 1.f / l_i[1]};
#pragma unroll
    for (int db = 0; db < 16; db++) {
#pragma unroll
        for (int r = 0; r < 2; r++) {
            int row = q0 + wq * 16 + g + r * 8;
            size_t zoff = ((size_t)b_ * N_ + row) * D_ + h * DK_ + db * 8 + t4 * 2;
            uint32_t hi, lo;
            pack_hilo(o[db][r * 2] * inv[r], o[db][r * 2 + 1] * inv[r], hi, lo);
            *(uint32_t*)(Zh + zoff) = hi;
            *(uint32_t*)(Zl + zoff) = lo;
        }
    }
}

// ---------------------------------------------------------------------------
// Host launcher (graph-capturable: kernel launches only)
// ---------------------------------------------------------------------------
extern "C" void kernel_launch(void* const* d_in, const int* in_sizes, int n_in,
                              void* d_out, int out_size)
{
    (void)in_sizes; (void)n_in; (void)out_size;
    const float* x     = (const float*)d_in[0];
    const float* Wq    = (const float*)d_in[1];
    const float* Wk    = (const float*)d_in[2];
    const float* Wv    = (const float*)d_in[3];
    const float* U     = (const float*)d_in[4];
    const float* Wproj = (const float*)d_in[5];
    float* out = (float*)d_out;

    __nv_bfloat16 *xh, *xl, *WUqh, *WUql, *WUkh, *WUkl, *Wvh, *Wvl, *Wph, *Wpl;
    __nv_bfloat16 *Qh, *Ql, *Kh, *Kl, *Vh, *Vl, *Zh, *Zl;
    cudaGetSymbolAddress((void**)&xh,   g_xh);
    cudaGetSymbolAddress((void**)&xl,   g_xl);
    cudaGetSymbolAddress((void**)&WUqh, g_WUqh);
    cudaGetSymbolAddress((void**)&WUql, g_WUql);
    cudaGetSymbolAddress((void**)&WUkh, g_WUkh);
    cudaGetSymbolAddress((void**)&WUkl, g_WUkl);
    cudaGetSymbolAddress((void**)&Wvh,  g_Wvh);
    cudaGetSymbolAddress((void**)&Wvl,  g_Wvl);
    cudaGetSymbolAddress((void**)&Wph,  g_Wph);
    cudaGetSymbolAddress((void**)&Wpl,  g_Wpl);
    cudaGetSymbolAddress((void**)&Qh,   g_Qh);
    cudaGetSymbolAddress((void**)&Ql,   g_Ql);
    cudaGetSymbolAddress((void**)&Kh,   g_Kh);
    cudaGetSymbolAddress((void**)&Kl,   g_Kl);
    cudaGetSymbolAddress((void**)&Vh,   g_Vh);
    cudaGetSymbolAddress((void**)&Vl,   g_Vl);
    cudaGetSymbolAddress((void**)&Zh,   g_Zh);
    cudaGetSymbolAddress((void**)&Zl,   g_Zl);

    cudaFuncSetAttribute(gemm_cp_bf16x3<1, R_>,
                         cudaFuncAttributeMaxDynamicSharedMemorySize, GEMM_SMEM);
    cudaFuncSetAttribute(gemm_cp_bf16x3<1, DK_>,
                         cudaFuncAttributeMaxDynamicSharedMemorySize, GEMM_SMEM);
    cudaFuncSetAttribute(gemm_cp_bf16x3<0, 1>,
                         cudaFuncAttributeMaxDynamicSharedMemorySize, GEMM_SMEM);
    cudaFuncSetAttribute(flash_cp_kernel,
                         cudaFuncAttributeMaxDynamicSharedMemorySize, FLM_SMEM);

    const float qscale = rsqrtf((float)DK_);

    // 0) one-time splits + U-folding
    split_bf16_kernel<<<(M_ * D_ / 4) / 256, 256>>>(
        (const float4*)x, (uint2*)xh, (uint2*)xl, M_ * D_ / 4);
    split_bf16_kernel<<<(D_ * D_ / 4) / 256, 256>>>(
        (const float4*)Wv, (uint2*)Wvh, (uint2*)Wvl, D_ * D_ / 4);
    split_bf16_kernel<<<(D_ * D_ / 4) / 256, 256>>>(
        (const float4*)Wproj, (uint2*)Wph, (uint2*)Wpl, D_ * D_ / 4);
    build_wu_kernel<<<dim3(D_ / 256, H_, 4), 256>>>(Wq, U, WUqh, WUql);
    build_wu_kernel<<<dim3(D_ / 256, H_, 4), 256>>>(Wk, U, WUkh, WUkl);

    // 1) Q = (x @ WUq^T) * 1/sqrt(dk) -> bf16 hi/lo [b,h,n,r]
    gemm_cp_bf16x3<1, R_><<<dim3(HR_ / 256, M_ / 128), 256, GEMM_SMEM>>>(
        xh, xl, WUqh, WUql, nullptr, Qh, Ql, HR_, D_, qscale);
    // 2) K = x @ WUk^T -> bf16 hi/lo
    gemm_cp_bf16x3<1, R_><<<dim3(HR_ / 256, M_ / 128), 256, GEMM_SMEM>>>(
        xh, xl, WUkh, WUkl, nullptr, Kh, Kl, HR_, D_, 1.0f);
    // 3) V = x @ Wv^T -> bf16 hi/lo [b,h,n,dk]
    gemm_cp_bf16x3<1, DK_><<<dim3(D_ / 256, M_ / 128), 256, GEMM_SMEM>>>(
        xh, xl, Wvh, Wvl, nullptr, Vh, Vl, D_, D_, 1.0f);

    // 4) flash attention with ALiBi -> Z bf16 hi/lo [b,n,d]
    flash_cp_kernel<<<dim3(N_ / 128, B_ * H_), 256, FLM_SMEM>>>(
        Qh, Ql, Kh, Kl, Vh, Vl, Zh, Zl);

    // 5) out = Z @ Wproj^T -> fp32
    gemm_cp_bf16x3<0, 1><<<dim3(D_ / 256, M_ / 128), 256, GEMM_SMEM>>>(
        Zh, Zl, Wph, Wpl, out, nullptr, nullptr, D_, D_, 1.0f);
}

// round 11
// speedup vs baseline: 1.0464x; 1.0464x over previous
#include <cuda_runtime.h>
#include <cuda_bf16.h>
#include <math.h>
#include <stdint.h>

// ---------------------------------------------------------------------------
// Problem constants (B=4, N=2048, D=2048, H=16, DK=128, R=32)
// ---------------------------------------------------------------------------
#define B_   4
#define N_   2048
#define D_   2048
#define H_   16
#define DK_  128
#define R_   32
#define M_   (B_ * N_)      // 8192
#define HR_  (H_ * R_)      // 512

// ---------------------------------------------------------------------------
// Device scratch (bf16 hi/lo everywhere between stages)
// ---------------------------------------------------------------------------
__device__ __nv_bfloat16 g_xh [(size_t)M_ * D_];
__device__ __nv_bfloat16 g_xl [(size_t)M_ * D_];
__device__ __nv_bfloat16 g_WUqh[(size_t)HR_ * D_];
__device__ __nv_bfloat16 g_WUql[(size_t)HR_ * D_];
__device__ __nv_bfloat16 g_WUkh[(size_t)HR_ * D_];
__device__ __nv_bfloat16 g_WUkl[(size_t)HR_ * D_];
__device__ __nv_bfloat16 g_Wvh[(size_t)D_ * D_];
__device__ __nv_bfloat16 g_Wvl[(size_t)D_ * D_];
__device__ __nv_bfloat16 g_Wph[(size_t)D_ * D_];
__device__ __nv_bfloat16 g_Wpl[(size_t)D_ * D_];
__device__ __nv_bfloat16 g_Qh[(size_t)B_ * H_ * N_ * R_];
__device__ __nv_bfloat16 g_Ql[(size_t)B_ * H_ * N_ * R_];
__device__ __nv_bfloat16 g_Kh[(size_t)B_ * H_ * N_ * R_];
__device__ __nv_bfloat16 g_Kl[(size_t)B_ * H_ * N_ * R_];
__device__ __nv_bfloat16 g_Vh[(size_t)B_ * H_ * N_ * DK_];
__device__ __nv_bfloat16 g_Vl[(size_t)B_ * H_ * N_ * DK_];
__device__ __nv_bfloat16 g_Zh[(size_t)M_ * D_];
__device__ __nv_bfloat16 g_Zl[(size_t)M_ * D_];

// ---------------------------------------------------------------------------
// PTX wrappers (sm_80-era, valid on plain sm_103 target)
// ---------------------------------------------------------------------------
__device__ __forceinline__ uint32_t smem_u32(const void* p) {
    uint32_t a;
    asm("{ .reg .u64 t; cvta.to.shared.u64 t, %1; cvt.u32.u64 %0, t; }"
        : "=r"(a) : "l"(p));
    return a;
}
__device__ __forceinline__ void ldsm_x4(uint32_t* r, uint32_t addr) {
    asm volatile("ldmatrix.sync.aligned.m8n8.x4.shared.b16 {%0,%1,%2,%3}, [%4];"
                 : "=r"(r[0]), "=r"(r[1]), "=r"(r[2]), "=r"(r[3]) : "r"(addr));
}
__device__ __forceinline__ void ldsm_x2(uint32_t* r, uint32_t addr) {
    asm volatile("ldmatrix.sync.aligned.m8n8.x2.shared.b16 {%0,%1}, [%2];"
                 : "=r"(r[0]), "=r"(r[1]) : "r"(addr));
}
__device__ __forceinline__ void ldsm_x4_t(uint32_t* r, uint32_t addr) {
    asm volatile("ldmatrix.sync.aligned.m8n8.x4.trans.shared.b16 {%0,%1,%2,%3}, [%4];"
                 : "=r"(r[0]), "=r"(r[1]), "=r"(r[2]), "=r"(r[3]) : "r"(addr));
}
__device__ __forceinline__ void mma_bf16(float* d, const uint32_t* a, const uint32_t* b) {
    asm volatile(
        "mma.sync.aligned.m16n8k16.row.col.f32.bf16.bf16.f32 "
        "{%0,%1,%2,%3}, {%4,%5,%6,%7}, {%8,%9}, {%0,%1,%2,%3};"
        : "+f"(d[0]), "+f"(d[1]), "+f"(d[2]), "+f"(d[3])
        : "r"(a[0]), "r"(a[1]), "r"(a[2]), "r"(a[3]), "r"(b[0]), "r"(b[1]));
}
__device__ __forceinline__ void cp16(uint32_t dst, const void* src) {
    asm volatile("cp.async.cg.shared.global [%0], [%1], 16;"
                 :: "r"(dst), "l"(src) : "memory");
}
#define CP_COMMIT() asm volatile("cp.async.commit_group;" ::: "memory")
#define CP_WAITG(n) asm volatile("cp.async.wait_group %0;" :: "n"(n) : "memory")

__device__ __forceinline__ void split2(float x, __nv_bfloat16& h, __nv_bfloat16& l) {
    h = __float2bfloat16(x);
    l = __float2bfloat16(x - __bfloat162float(h));
}
__device__ __forceinline__ uint32_t packbf(__nv_bfloat16 a, __nv_bfloat16 b) {
    return (uint32_t)__bfloat16_as_ushort(a) | ((uint32_t)__bfloat16_as_ushort(b) << 16);
}
__device__ __forceinline__ void pack_hilo(float x, float y, uint32_t& hi, uint32_t& lo) {
    __nv_bfloat16 hx, lx, hy, ly;
    split2(x, hx, lx); split2(y, hy, ly);
    hi = packbf(hx, hy); lo = packbf(lx, ly);
}

// ---------------------------------------------------------------------------
// Prep kernels
// ---------------------------------------------------------------------------
__global__ void split_bf16_kernel(const float4* __restrict__ in,
                                  uint2* __restrict__ hi, uint2* __restrict__ lo, int n4)
{
    int i = blockIdx.x * 256 + threadIdx.x;
    if (i >= n4) return;
    float4 v = in[i];
    __nv_bfloat16 h0, h1, h2, h3, l0, l1, l2, l3;
    split2(v.x, h0, l0); split2(v.y, h1, l1);
    split2(v.z, h2, l2); split2(v.w, h3, l3);
    hi[i] = make_uint2(packbf(h0, h1), packbf(h2, h3));
    lo[i] = make_uint2(packbf(l0, l1), packbf(l2, l3));
}

// WU[h*32 + r, d] = sum_dk W[h*128+dk, d] * U[dk, r]; each thread does 8 r's.
__global__ void build_wu_kernel(const float* __restrict__ W,
                                const float* __restrict__ U,
                                __nv_bfloat16* __restrict__ WUh,
                                __nv_bfloat16* __restrict__ WUl)
{
    __shared__ float Us[128][8];
    const int tid = threadIdx.x;
    const int d   = blockIdx.x * 256 + tid;
    const int h   = blockIdx.y;
    const int rg  = blockIdx.z;

    for (int i = tid; i < 128 * 8; i += 256) {
        int dk = i >> 3, j = i & 7;
        Us[dk][j] = U[dk * R_ + rg * 8 + j];
    }
    __syncthreads();

    const float* wcol = W + (size_t)h * DK_ * D_ + d;
    float acc[8];
#pragma unroll
    for (int j = 0; j < 8; j++) acc[j] = 0.f;
#pragma unroll 4
    for (int dk = 0; dk < DK_; dk++) {
        float w = wcol[(size_t)dk * D_];
#pragma unroll
        for (int j = 0; j < 8; j++) acc[j] = fmaf(w, Us[dk][j], acc[j]);
    }
#pragma unroll
    for (int j = 0; j < 8; j++) {
        __nv_bfloat16 hh, ll;
        split2(acc[j], hh, ll);
        size_t off = (size_t)(h * 32 + rg * 8 + j) * D_ + d;
        WUh[off] = hh;
        WUl[off] = ll;
    }
}

// ---------------------------------------------------------------------------
// HMMA 3xBF16 GEMM v5: CTA 128x128, warp 64x32 (16 warps/SM), BK=16,
// 4-stage cp.async pipeline (prefetch distance 3 iters >= DRAM latency),
// single barrier per iteration.
// smem/stage: Ah@0 Al@6144 Bh@12288 Bl@18432, rows 48B (conflict-free ldsm).
// MODE 0: fp32 C[m*NN+n]
// MODE 1: bf16 hi/lo head-split (scaled)
// ---------------------------------------------------------------------------
#define STG_SIZE 24576
#define GEMM_SMEM (4 * STG_SIZE)    // 98304 -> 2 CTAs/SM

template <int MODE, int SPLIT>
__global__ void __launch_bounds__(256, 2)
gemm_cp_bf16x3(const __nv_bfloat16* __restrict__ Ah,
               const __nv_bfloat16* __restrict__ Al,
               const __nv_bfloat16* __restrict__ Bh,
               const __nv_bfloat16* __restrict__ Bl,
               float* __restrict__ Cf,
               __nv_bfloat16* __restrict__ Ch,
               __nv_bfloat16* __restrict__ Cl,
               int NN, int K, float scale)
{
    extern __shared__ char sm[];
    const uint32_t sb = smem_u32(sm);

    const int tid  = threadIdx.x;
    const int lane = tid & 31;
    const int wid  = tid >> 5;
    const int wm   = wid & 1;
    const int wn   = wid >> 1;
    const int m0   = blockIdx.y * 128;
    const int n0   = blockIdx.x * 128;

    const __nv_bfloat16* bases[4] = {
        Ah + (size_t)m0 * K, Al + (size_t)m0 * K,
        Bh + (size_t)n0 * K, Bl + (size_t)n0 * K };

    // per-iteration stage load: 1024 16B chunks (4 parts x 128 rows x 2)
    auto issue = [&](int st, int it) {
        const uint32_t stb = sb + (uint32_t)st * STG_SIZE;
#pragma unroll
        for (int v = 0; v < 4; v++) {
            int idx = v * 256 + tid;        // 0..1023
            int p   = idx >> 8;             // part
            int r   = (idx >> 1) & 127;     // row
            int q   = idx & 1;              // 16B chunk within row
            const __nv_bfloat16* src = bases[p] + (size_t)r * K + it * 16 + q * 8;
            cp16(stb + p * 6144 + (uint32_t)(r * 48 + q * 16), src);
        }
    };

    const int niter = K / 16;
    issue(0, 0); CP_COMMIT();
    issue(1, 1); CP_COMMIT();
    issue(2, 2); CP_COMMIT();

    float acc[4][4][4];
#pragma unroll
    for (int mi = 0; mi < 4; mi++)
#pragma unroll
        for (int ni = 0; ni < 4; ni++)
#pragma unroll
            for (int f = 0; f < 4; f++) acc[mi][ni][f] = 0.f;

    const uint32_t a_off =
        (uint32_t)((wm * 64 + (lane & 15)) * 48 + (lane >> 4) * 16);
    const uint32_t b_off = 12288u +
        (uint32_t)((wn * 32 + (lane & 7)) * 48 + ((lane >> 3) & 1) * 16);

    for (int it = 0; it < niter; ++it) {
        CP_WAITG(2);
        __syncthreads();
        if (it + 3 < niter) { issue((it + 3) & 3, it + 3); CP_COMMIT(); }

        const uint32_t stb = sb + (uint32_t)(it & 3) * STG_SIZE;
        const uint32_t a_addr = stb + a_off;
        const uint32_t b_addr = stb + b_off;

        uint32_t ah[4][4], al[4][4];
#pragma unroll
        for (int mi = 0; mi < 4; mi++) {
            uint32_t off = (uint32_t)(mi * 768);   // 16 rows * 48B
            ldsm_x4(ah[mi], a_addr + off);
            ldsm_x4(al[mi], a_addr + off + 6144);
        }
#pragma unroll
        for (int ni = 0; ni < 4; ni++) {
            uint32_t bh[2], bl[2];
            uint32_t off = (uint32_t)(ni * 384);   // 8 rows * 48B
            ldsm_x2(bh, b_addr + off);
            ldsm_x2(bl, b_addr + off + 6144);
#pragma unroll
            for (int mi = 0; mi < 4; mi++) {
                mma_bf16(acc[mi][ni], ah[mi], bh);
                mma_bf16(acc[mi][ni], ah[mi], bl);
                mma_bf16(acc[mi][ni], al[mi], bh);
            }
        }
    }

    // epilogue
    const int g  = lane >> 2;
    const int c2 = (lane & 3) * 2;
#pragma unroll
    for (int mi = 0; mi < 4; mi++) {
#pragma unroll
        for (int ni = 0; ni < 4; ni++) {
            int m = m0 + wm * 64 + mi * 16 + g;
            int n = n0 + wn * 32 + ni * 8 + c2;
#pragma unroll
            for (int half = 0; half < 2; half++) {
                int mm = m + half * 8;
                float v0 = acc[mi][ni][half * 2];
                float v1 = acc[mi][ni][half * 2 + 1];
                if (MODE == 0) {
                    *(float2*)(Cf + (size_t)mm * NN + n) = make_float2(v0, v1);
                } else {
                    int b_ = mm >> 11;
                    int t  = mm & (N_ - 1);
                    int h  = n / SPLIT;
                    int j  = n % SPLIT;
                    size_t off = (((size_t)(b_ * H_ + h)) * N_ + t) * SPLIT + j;
                    uint32_t hi, lo;
                    pack_hilo(v0 * scale, v1 * scale, hi, lo);
                    *(uint32_t*)(Ch + off) = hi;
                    *(uint32_t*)(Cl + off) = lo;
                }
            }
        }
    }
}

// ---------------------------------------------------------------------------
// HMMA flash attention (unchanged from R9; proven, rel_err 2.2e-5)
// ---------------------------------------------------------------------------
#define FQ_H 0
#define FQ_L 10240
#define FK_BASE 20480
#define FK_STAGE 20480
#define FV_BASE 61440
#define FV_STAGE 69632
#define FLM_SMEM 200704
#define VSTR 272

__global__ void __launch_bounds__(256, 1)
flash_cp_kernel(const __nv_bfloat16* __restrict__ Qh, const __nv_bfloat16* __restrict__ Ql,
                const __nv_bfloat16* __restrict__ Kh, const __nv_bfloat16* __restrict__ Kl,
                const __nv_bfloat16* __restrict__ Vh, const __nv_bfloat16* __restrict__ Vl,
                __nv_bfloat16* __restrict__ Zh, __nv_bfloat16* __restrict__ Zl)
{
    extern __shared__ char sm[];
    const uint32_t sb = smem_u32(sm);

    const int tid  = threadIdx.x;
    const int lane = tid & 31;
    const int wq   = tid >> 5;
    const int bh   = blockIdx.y;
    const int h    = bh & (H_ - 1);
    const int b_   = bh >> 4;
    const int q0   = blockIdx.x * 128;
    const int g    = lane >> 2;
    const int t4   = lane & 3;

    const float slope = exp2f(-0.5f * (float)(h + 1));
    const float NEG_INF = -__int_as_float(0x7f800000);

    auto issue_kv = [&](int st, int kt2) {
        const int k0 = kt2 * 128;
        const __nv_bfloat16* kh = Kh + ((size_t)bh * N_ + k0) * R_;
        const __nv_bfloat16* kl = Kl + ((size_t)bh * N_ + k0) * R_;
#pragma unroll
        for (int v = 0; v < 4; v++) {
            int idx = (v & 1) * 256 + tid;
            int row = idx >> 2, q = idx & 3;
            const __nv_bfloat16* src = (v < 2 ? kh : kl) + (size_t)row * R_ + q * 8;
            uint32_t dst = sb + FK_BASE + st * FK_STAGE + (v < 2 ? 0 : 10240)
                         + (uint32_t)(row * 80 + q * 16);
            cp16(dst, src);
        }
        const __nv_bfloat16* vh = Vh + ((size_t)bh * N_ + k0) * DK_;
        const __nv_bfloat16* vl = Vl + ((size_t)bh * N_ + k0) * DK_;
#pragma unroll
        for (int v = 0; v < 16; v++) {
            int idx = (v & 7) * 256 + tid;
            int row = idx >> 4, q = idx & 15;
            const __nv_bfloat16* src = (v < 8 ? vh : vl) + (size_t)row * DK_ + q * 8;
            uint32_t dst = sb + FV_BASE + st * FV_STAGE + (v < 8 ? 0 : 34816)
                         + (uint32_t)(row * VSTR + q * 16);
            cp16(dst, src);
        }
    };

    {
        const __nv_bfloat16* qh_ = Qh + ((size_t)bh * N_ + q0) * R_;
        const __nv_bfloat16* ql_ = Ql + ((size_t)bh * N_ + q0) * R_;
#pragma unroll
        for (int v = 0; v < 4; v++) {
            int idx = (v & 1) * 256 + tid;
            int row = idx >> 2, q = idx & 3;
            const __nv_bfloat16* src = (v < 2 ? qh_ : ql_) + (size_t)row * R_ + q * 8;
            uint32_t dst = sb + (v < 2 ? FQ_H : FQ_L) + (uint32_t)(row * 80 + q * 16);
            cp16(dst, src);
        }
    }
    CP_COMMIT();
    issue_kv(0, 0); CP_COMMIT();
    issue_kv(1, 1); CP_COMMIT();

    CP_WAITG(2);
    __syncthreads();

    uint32_t qh[2][4], ql[2][4];
    {
        uint32_t qaddr = sb + FQ_H +
            (uint32_t)((wq * 16 + (lane & 15)) * 40 + (lane >> 4) * 8) * 2;
#pragma unroll
        for (int ks = 0; ks < 2; ks++) {
            ldsm_x4(qh[ks], qaddr + ks * 32);
            ldsm_x4(ql[ks], qaddr + ks * 32 + 10240);
        }
    }

    float o[16][4];
#pragma unroll
    for (int d = 0; d < 16; d++)
#pragma unroll
        for (int f = 0; f < 4; f++) o[d][f] = 0.f;
    float m_i[2] = {NEG_INF, NEG_INF};
    float l_i[2] = {0.f, 0.f};

    for (int kt = 0; kt < N_ / 128; kt++) {
        const int k0 = kt * 128;
        CP_WAITG(1);
        __syncthreads();
        const int st = kt & 1;

        float s[16][4];
#pragma unroll
        for (int nb = 0; nb < 16; nb++)
#pragma unroll
            for (int f = 0; f < 4; f++) s[nb][f] = 0.f;

        {
            uint32_t baddr = sb + FK_BASE + st * FK_STAGE +
                (uint32_t)((lane & 7) * 40 + ((lane >> 3) & 1) * 8) * 2;
#pragma unroll
            for (int ks = 0; ks < 2; ks++) {
#pragma unroll
                for (int nb = 0; nb < 16; nb++) {
                    uint32_t bhh[2], bll[2];
                    uint32_t off = (uint32_t)(nb * 640 + ks * 32);
                    ldsm_x2(bhh, baddr + off);
                    ldsm_x2(bll, baddr + off + 10240);
                    mma_bf16(s[nb], qh[ks], bhh);
                    mma_bf16(s[nb], qh[ks], bll);
                    mma_bf16(s[nb], ql[ks], bhh);
                }
            }
        }

#pragma unroll
        for (int nb = 0; nb < 16; nb++) {
#pragma unroll
            for (int f = 0; f < 4; f++) {
                int r = f >> 1, c = f & 1;
                int jg = k0 + nb * 8 + t4 * 2 + c;
                int ig = q0 + wq * 16 + g + r * 8;
                s[nb][f] -= slope * fmaxf((float)(jg - ig), 0.f);
            }
        }

        float alpha[2], mnew[2];
#pragma unroll
        for (int r = 0; r < 2; r++) {
            float tm = NEG_INF;
#pragma unroll
            for (int nb = 0; nb < 16; nb++) {
                tm = fmaxf(tm, s[nb][r * 2]);
                tm = fmaxf(tm, s[nb][r * 2 + 1]);
            }
            tm = fmaxf(tm, __shfl_xor_sync(0xffffffffu, tm, 1));
            tm = fmaxf(tm, __shfl_xor_sync(0xffffffffu, tm, 2));
            mnew[r]  = fmaxf(m_i[r], tm);
            alpha[r] = __expf(m_i[r] - mnew[r]);
            m_i[r]   = mnew[r];
        }

        float rsum[2] = {0.f, 0.f};
#pragma unroll
        for (int nb = 0; nb < 16; nb++) {
#pragma unroll
            for (int f = 0; f < 4; f++) {
                int r = f >> 1;
                float p = __expf(s[nb][f] - mnew[r]);
                s[nb][f] = p;
                rsum[r] += p;
            }
        }
#pragma unroll
        for (int r = 0; r < 2; r++) {
            rsum[r] += __shfl_xor_sync(0xffffffffu, rsum[r], 1);
            rsum[r] += __shfl_xor_sync(0xffffffffu, rsum[r], 2);
            l_i[r] = l_i[r] * alpha[r] + rsum[r];
        }
#pragma unroll
        for (int d = 0; d < 16; d++)
#pragma unroll
            for (int f = 0; f < 4; f++) o[d][f] *= alpha[f >> 1];

        {
            uint32_t vaddr = sb + FV_BASE + st * FV_STAGE +
                (uint32_t)((lane & 15) * VSTR + (lane >> 4) * 16);
#pragma unroll
            for (int ks = 0; ks < 8; ks++) {
                uint32_t aH[4], aL[4];
                pack_hilo(s[2 * ks][0],     s[2 * ks][1],     aH[0], aL[0]);
                pack_hilo(s[2 * ks][2],     s[2 * ks][3],     aH[1], aL[1]);
                pack_hilo(s[2 * ks + 1][0], s[2 * ks + 1][1], aH[2], aL[2]);
                pack_hilo(s[2 * ks + 1][2], s[2 * ks + 1][3], aH[3], aL[3]);
#pragma unroll
                for (int db = 0; db < 8; db++) {
                    uint32_t vh4[4], vl4[4];
                    uint32_t off = (uint32_t)(ks * 16 * VSTR + db * 32);
                    ldsm_x4_t(vh4, vaddr + off);
                    ldsm_x4_t(vl4, vaddr + off + 34816);
                    mma_bf16(o[db * 2],     aH, vh4);
                    mma_bf16(o[db * 2],     aH, vl4);
                    mma_bf16(o[db * 2],     aL, vh4);
                    mma_bf16(o[db * 2 + 1], aH, vh4 + 2);
                    mma_bf16(o[db * 2 + 1], aH, vl4 + 2);
                    mma_bf16(o[db * 2 + 1], aL, vh4 + 2);
                }
            }
        }
        __syncthreads();
        if (kt + 2 < N_ / 128) { issue_kv(st, kt + 2); CP_COMMIT(); }
    }

    float inv[2] = {1.f / l_i[0], 1.f / l_i[1]};
#pragma unroll
    for (int db = 0; db < 16; db++) {
#pragma unroll
        for (int r = 0; r < 2; r++) {
            int row = q0 + wq * 16 + g + r * 8;
            size_t zoff = ((size_t)b_ * N_ + row) * D_ + h * DK_ + db * 8 + t4 * 2;
            uint32_t hi, lo;
            pack_hilo(o[db][r * 2] * inv[r], o[db][r * 2 + 1] * inv[r], hi, lo);
            *(uint32_t*)(Zh + zoff) = hi;
            *(uint32_t*)(Zl + zoff) = lo;
        }
    }
}

// ---------------------------------------------------------------------------
// Host launcher (graph-capturable: kernel launches only)
// ---------------------------------------------------------------------------
extern "C" void kernel_launch(void* const* d_in, const int* in_sizes, int n_in,
                              void* d_out, int out_size)
{
    (void)in_sizes; (void)n_in; (void)out_size;
    const float* x     = (const float*)d_in[0];
    const float* Wq    = (const float*)d_in[1];
    const float* Wk    = (const float*)d_in[2];
    const float* Wv    = (const float*)d_in[3];
    const float* U     = (const float*)d_in[4];
    const float* Wproj = (const float*)d_in[5];
    float* out = (float*)d_out;

    __nv_bfloat16 *xh, *xl, *WUqh, *WUql, *WUkh, *WUkl, *Wvh, *Wvl, *Wph, *Wpl;
    __nv_bfloat16 *Qh, *Ql, *Kh, *Kl, *Vh, *Vl, *Zh, *Zl;
    cudaGetSymbolAddress((void**)&xh,   g_xh);
    cudaGetSymbolAddress((void**)&xl,   g_xl);
    cudaGetSymbolAddress((void**)&WUqh, g_WUqh);
    cudaGetSymbolAddress((void**)&WUql, g_WUql);
    cudaGetSymbolAddress((void**)&WUkh, g_WUkh);
    cudaGetSymbolAddress((void**)&WUkl, g_WUkl);
    cudaGetSymbolAddress((void**)&Wvh,  g_Wvh);
    cudaGetSymbolAddress((void**)&Wvl,  g_Wvl);
    cudaGetSymbolAddress((void**)&Wph,  g_Wph);
    cudaGetSymbolAddress((void**)&Wpl,  g_Wpl);
    cudaGetSymbolAddress((void**)&Qh,   g_Qh);
    cudaGetSymbolAddress((void**)&Ql,   g_Ql);
    cudaGetSymbolAddress((void**)&Kh,   g_Kh);
    cudaGetSymbolAddress((void**)&Kl,   g_Kl);
    cudaGetSymbolAddress((void**)&Vh,   g_Vh);
    cudaGetSymbolAddress((void**)&Vl,   g_Vl);
    cudaGetSymbolAddress((void**)&Zh,   g_Zh);
    cudaGetSymbolAddress((void**)&Zl,   g_Zl);

    cudaFuncSetAttribute(gemm_cp_bf16x3<1, R_>,
                         cudaFuncAttributeMaxDynamicSharedMemorySize, GEMM_SMEM);
    cudaFuncSetAttribute(gemm_cp_bf16x3<1, DK_>,
                         cudaFuncAttributeMaxDynamicSharedMemorySize, GEMM_SMEM);
    cudaFuncSetAttribute(gemm_cp_bf16x3<0, 1>,
                         cudaFuncAttributeMaxDynamicSharedMemorySize, GEMM_SMEM);
    cudaFuncSetAttribute(flash_cp_kernel,
                         cudaFuncAttributeMaxDynamicSharedMemorySize, FLM_SMEM);

    const float qscale = rsqrtf((float)DK_);

    // 0) one-time splits + U-folding
    split_bf16_kernel<<<(M_ * D_ / 4) / 256, 256>>>(
        (const float4*)x, (uint2*)xh, (uint2*)xl, M_ * D_ / 4);
    split_bf16_kernel<<<(D_ * D_ / 4) / 256, 256>>>(
        (const float4*)Wv, (uint2*)Wvh, (uint2*)Wvl, D_ * D_ / 4);
    split_bf16_kernel<<<(D_ * D_ / 4) / 256, 256>>>(
        (const float4*)Wproj, (uint2*)Wph, (uint2*)Wpl, D_ * D_ / 4);
    build_wu_kernel<<<dim3(D_ / 256, H_, 4), 256>>>(Wq, U, WUqh, WUql);
    build_wu_kernel<<<dim3(D_ / 256, H_, 4), 256>>>(Wk, U, WUkh, WUkl);

    // 1) Q = (x @ WUq^T) * 1/sqrt(dk) -> bf16 hi/lo [b,h,n,r]
    gemm_cp_bf16x3<1, R_><<<dim3(HR_ / 128, M_ / 128), 256, GEMM_SMEM>>>(
        xh, xl, WUqh, WUql, nullptr, Qh, Ql, HR_, D_, qscale);
    // 2) K = x @ WUk^T -> bf16 hi/lo
    gemm_cp_bf16x3<1, R_><<<dim3(HR_ / 128, M_ / 128), 256, GEMM_SMEM>>>(
        xh, xl, WUkh, WUkl, nullptr, Kh, Kl, HR_, D_, 1.0f);
    // 3) V = x @ Wv^T -> bf16 hi/lo [b,h,n,dk]
    gemm_cp_bf16x3<1, DK_><<<dim3(D_ / 128, M_ / 128), 256, GEMM_SMEM>>>(
        xh, xl, Wvh, Wvl, nullptr, Vh, Vl, D_, D_, 1.0f);

    // 4) flash attention with ALiBi -> Z bf16 hi/lo [b,n,d]
    flash_cp_kernel<<<dim3(N_ / 128, B_ * H_), 256, FLM_SMEM>>>(
        Qh, Ql, Kh, Kl, Vh, Vl, Zh, Zl);

    // 5) out = Z @ Wproj^T -> fp32
    gemm_cp_bf16x3<0, 1><<<dim3(D_ / 128, M_ / 128), 256, GEMM_SMEM>>>(
        Zh, Zl, Wph, Wpl, out, nullptr, nullptr, D_, D_, 1.0f);
}

// round 12
// speedup vs baseline: 1.4200x; 1.3570x over previous
#include <cuda_runtime.h>
#include <cuda_fp16.h>
#include <math.h>
#include <stdint.h>

// ---------------------------------------------------------------------------
// Problem constants (B=4, N=2048, D=2048, H=16, DK=128, R=32)
// ---------------------------------------------------------------------------
#define B_   4
#define N_   2048
#define D_   2048
#define H_   16
#define DK_  128
#define R_   32
#define M_   (B_ * N_)      // 8192
#define HR_  (H_ * R_)      // 512

// ---------------------------------------------------------------------------
// Device scratch (fp16; A-operands plain, B-operands hi/lo)
// ---------------------------------------------------------------------------
__device__ __half g_xh  [(size_t)M_ * D_];
__device__ __half g_WUqh[(size_t)HR_ * D_];
__device__ __half g_WUql[(size_t)HR_ * D_];
__device__ __half g_WUkh[(size_t)HR_ * D_];
__device__ __half g_WUkl[(size_t)HR_ * D_];
__device__ __half g_Wvh [(size_t)D_ * D_];
__device__ __half g_Wvl [(size_t)D_ * D_];
__device__ __half g_Wph [(size_t)D_ * D_];
__device__ __half g_Wpl [(size_t)D_ * D_];
__device__ __half g_Qh  [(size_t)B_ * H_ * N_ * R_];
__device__ __half g_Ql  [(size_t)B_ * H_ * N_ * R_];   // written, unused
__device__ __half g_Kh  [(size_t)B_ * H_ * N_ * R_];
__device__ __half g_Kl  [(size_t)B_ * H_ * N_ * R_];
__device__ __half g_Vh  [(size_t)B_ * H_ * N_ * DK_];
__device__ __half g_Vl  [(size_t)B_ * H_ * N_ * DK_];
__device__ __half g_Zh  [(size_t)M_ * D_];

// ---------------------------------------------------------------------------
// PTX wrappers (sm_80-era, valid on plain sm_103 target)
// ---------------------------------------------------------------------------
__device__ __forceinline__ uint32_t smem_u32(const void* p) {
    uint32_t a;
    asm("{ .reg .u64 t; cvta.to.shared.u64 t, %1; cvt.u32.u64 %0, t; }"
        : "=r"(a) : "l"(p));
    return a;
}
__device__ __forceinline__ void ldsm_x4(uint32_t* r, uint32_t addr) {
    asm volatile("ldmatrix.sync.aligned.m8n8.x4.shared.b16 {%0,%1,%2,%3}, [%4];"
                 : "=r"(r[0]), "=r"(r[1]), "=r"(r[2]), "=r"(r[3]) : "r"(addr));
}
__device__ __forceinline__ void ldsm_x2(uint32_t* r, uint32_t addr) {
    asm volatile("ldmatrix.sync.aligned.m8n8.x2.shared.b16 {%0,%1}, [%2];"
                 : "=r"(r[0]), "=r"(r[1]) : "r"(addr));
}
__device__ __forceinline__ void ldsm_x4_t(uint32_t* r, uint32_t addr) {
    asm volatile("ldmatrix.sync.aligned.m8n8.x4.trans.shared.b16 {%0,%1,%2,%3}, [%4];"
                 : "=r"(r[0]), "=r"(r[1]), "=r"(r[2]), "=r"(r[3]) : "r"(addr));
}
__device__ __forceinline__ void mma_f16(float* d, const uint32_t* a, const uint32_t* b) {
    asm volatile(
        "mma.sync.aligned.m16n8k16.row.col.f32.f16.f16.f32 "
        "{%0,%1,%2,%3}, {%4,%5,%6,%7}, {%8,%9}, {%0,%1,%2,%3};"
        : "+f"(d[0]), "+f"(d[1]), "+f"(d[2]), "+f"(d[3])
        : "r"(a[0]), "r"(a[1]), "r"(a[2]), "r"(a[3]), "r"(b[0]), "r"(b[1]));
}
__device__ __forceinline__ void cp16(uint32_t dst, const void* src) {
    asm volatile("cp.async.cg.shared.global [%0], [%1], 16;"
                 :: "r"(dst), "l"(src) : "memory");
}
#define CP_COMMIT() asm volatile("cp.async.commit_group;" ::: "memory")
#define CP_WAITG(n) asm volatile("cp.async.wait_group %0;" :: "n"(n) : "memory")

__device__ __forceinline__ uint32_t packh2(float x, float y) {
    __half2 hh = __floats2half2_rn(x, y);
    return *reinterpret_cast<uint32_t*>(&hh);
}
__device__ __forceinline__ void split2h(float x, __half& h, __half& l) {
    h = __float2half(x);
    l = __float2half(x - __half2float(h));
}
__device__ __forceinline__ uint32_t packh(__half a, __half b) {
    return (uint32_t)__half_as_ushort(a) | ((uint32_t)__half_as_ushort(b) << 16);
}

// ---------------------------------------------------------------------------
// Prep kernels
// ---------------------------------------------------------------------------
// fp32 -> plain fp16 (A operands)
__global__ void cvt_f16_kernel(const float4* __restrict__ in,
                               uint2* __restrict__ h, int n4)
{
    int i = blockIdx.x * 256 + threadIdx.x;
    if (i >= n4) return;
    float4 v = in[i];
    h[i] = make_uint2(packh2(v.x, v.y), packh2(v.z, v.w));
}

// fp32 -> fp16 hi/lo (B operands)
__global__ void split_f16_kernel(const float4* __restrict__ in,
                                 uint2* __restrict__ hi, uint2* __restrict__ lo, int n4)
{
    int i = blockIdx.x * 256 + threadIdx.x;
    if (i >= n4) return;
    float4 v = in[i];
    __half h0, h1, h2, h3, l0, l1, l2, l3;
    split2h(v.x, h0, l0); split2h(v.y, h1, l1);
    split2h(v.z, h2, l2); split2h(v.w, h3, l3);
    hi[i] = make_uint2(packh(h0, h1), packh(h2, h3));
    lo[i] = make_uint2(packh(l0, l1), packh(l2, l3));
}

// WU[h*32 + r, d] = sum_dk W[h*128+dk, d] * U[dk, r] -> fp16 hi/lo
__global__ void build_wu_kernel(const float* __restrict__ W,
                                const float* __restrict__ U,
                                __half* __restrict__ WUh,
                                __half* __restrict__ WUl)
{
    __shared__ float Us[128][8];
    const int tid = threadIdx.x;
    const int d   = blockIdx.x * 256 + tid;
    const int h   = blockIdx.y;
    const int rg  = blockIdx.z;

    for (int i = tid; i < 128 * 8; i += 256) {
        int dk = i >> 3, j = i & 7;
        Us[dk][j] = U[dk * R_ + rg * 8 + j];
    }
    __syncthreads();

    const float* wcol = W + (size_t)h * DK_ * D_ + d;
    float acc[8];
#pragma unroll
    for (int j = 0; j < 8; j++) acc[j] = 0.f;
#pragma unroll 4
    for (int dk = 0; dk < DK_; dk++) {
        float w = wcol[(size_t)dk * D_];
#pragma unroll
        for (int j = 0; j < 8; j++) acc[j] = fmaf(w, Us[dk][j], acc[j]);
    }
#pragma unroll
    for (int j = 0; j < 8; j++) {
        __half hh, ll;
        split2h(acc[j], hh, ll);
        size_t off = (size_t)(h * 32 + rg * 8 + j) * D_ + d;
        WUh[off] = hh;
        WUl[off] = ll;
    }
}

// ---------------------------------------------------------------------------
// HMMA 2xFP16 GEMM: C = A * B^T with A plain fp16, B split hi/lo.
//   C[m,n] = sum_k A[m,k]*(Bh[n,k]+Bl[n,k])
// CTA 128x128, BK=32, 8 warps (2x4), warp tile 64x32, 2-stage cp.async.
// smem/stage: A@0, Bh@10240, Bl@20480, rows padded to 80B. 2 CTAs/SM.
// MODE 0: fp32 C[m*NN+n]; MODE 1: fp16 hi/lo head-split (scaled).
// ---------------------------------------------------------------------------
#define SG_SIZE 30720
#define GEMM_SMEM (2 * SG_SIZE)

template <int MODE, int SPLIT>
__global__ void __launch_bounds__(256, 2)
gemm_f16x2(const __half* __restrict__ A_,
           const __half* __restrict__ Bh_,
           const __half* __restrict__ Bl_,
           float* __restrict__ Cf,
           __half* __restrict__ Ch,
           __half* __restrict__ Cl,
           int NN, int K, float scale)
{
    extern __shared__ char sm[];
    const uint32_t sb = smem_u32(sm);

    const int tid  = threadIdx.x;
    const int lane = tid & 31;
    const int wid  = tid >> 5;
    const int wm   = wid & 1;
    const int wn   = wid >> 1;
    const int m0   = blockIdx.y * 128;
    const int n0   = blockIdx.x * 128;

    const __half* bases[3] = {
        A_  + (size_t)m0 * K,
        Bh_ + (size_t)n0 * K,
        Bl_ + (size_t)n0 * K };

    // 1536 16B chunks per stage (3 parts x 128 rows x 4)
    auto issue = [&](int st, int it) {
        const uint32_t stb = sb + (uint32_t)st * SG_SIZE;
#pragma unroll
        for (int v = 0; v < 6; v++) {
            int idx = v * 256 + tid;       // 0..1535
            int p   = idx >> 9;            // part 0..2
            int rq  = idx & 511;
            int r   = rq >> 2, q = rq & 3;
            const __half* src = bases[p] + (size_t)r * K + it * 32 + q * 8;
            cp16(stb + (uint32_t)(p * 10240 + r * 80 + q * 16), src);
        }
    };

    const int niter = K / 32;
    issue(0, 0); CP_COMMIT();
    issue(1, 1); CP_COMMIT();

    float acc[4][4][4];
#pragma unroll
    for (int mi = 0; mi < 4; mi++)
#pragma unroll
        for (int ni = 0; ni < 4; ni++)
#pragma unroll
            for (int f = 0; f < 4; f++) acc[mi][ni][f] = 0.f;

    const uint32_t a_off =
        (uint32_t)((wm * 64 + (lane & 15)) * 80 + (lane >> 4) * 16);
    const uint32_t b_off = 10240u +
        (uint32_t)((wn * 32 + (lane & 7)) * 80 + ((lane >> 3) & 1) * 16);

    for (int it = 0; it < niter; ++it) {
        CP_WAITG(1);
        __syncthreads();
        const uint32_t stb = sb + (uint32_t)(it & 1) * SG_SIZE;
        const uint32_t a_addr = stb + a_off;
        const uint32_t b_addr = stb + b_off;

#pragma unroll
        for (int ks = 0; ks < 2; ks++) {
            uint32_t ah[4][4];
#pragma unroll
            for (int mi = 0; mi < 4; mi++)
                ldsm_x4(ah[mi], a_addr + (uint32_t)(mi * 1280 + ks * 32));
#pragma unroll
            for (int ni = 0; ni < 4; ni++) {
                uint32_t bh[2], bl[2];
                uint32_t off = (uint32_t)(ni * 640 + ks * 32);
                ldsm_x2(bh, b_addr + off);
                ldsm_x2(bl, b_addr + off + 10240);
#pragma unroll
                for (int mi = 0; mi < 4; mi++) {
                    mma_f16(acc[mi][ni], ah[mi], bh);
                    mma_f16(acc[mi][ni], ah[mi], bl);
                }
            }
        }
        __syncthreads();
        if (it + 2 < niter) { issue(it & 1, it + 2); CP_COMMIT(); }
    }

    // epilogue
    const int g  = lane >> 2;
    const int c2 = (lane & 3) * 2;
#pragma unroll
    for (int mi = 0; mi < 4; mi++) {
#pragma unroll
        for (int ni = 0; ni < 4; ni++) {
            int m = m0 + wm * 64 + mi * 16 + g;
            int n = n0 + wn * 32 + ni * 8 + c2;
#pragma unroll
            for (int half_ = 0; half_ < 2; half_++) {
                int mm = m + half_ * 8;
                float v0 = acc[mi][ni][half_ * 2];
                float v1 = acc[mi][ni][half_ * 2 + 1];
                if (MODE == 0) {
                    *(float2*)(Cf + (size_t)mm * NN + n) = make_float2(v0, v1);
                } else {
                    int b_ = mm >> 11;
                    int t  = mm & (N_ - 1);
                    int h  = n / SPLIT;
                    int j  = n % SPLIT;
                    size_t off = (((size_t)(b_ * H_ + h)) * N_ + t) * SPLIT + j;
                    __half h0, l0, h1, l1;
                    split2h(v0 * scale, h0, l0);
                    split2h(v1 * scale, h1, l1);
                    *(uint32_t*)(Ch + off) = packh(h0, h1);
                    *(uint32_t*)(Cl + off) = packh(l0, l1);
                }
            }
        }
    }
}

// ---------------------------------------------------------------------------
// HMMA flash attention (fp16 2-pass): Q plain fp16 in regs, K/V split hi/lo,
// P packed plain fp16 reg->reg, ALiBi inline, double-buffered cp.async K/V.
// smem: Q 10240 | K stages 2x20480 | V stages 2x69632 = 190464 B
// ---------------------------------------------------------------------------
#define FQ 0
#define FK_BASE 10240
#define FK_STAGE 20480
#define FV_BASE 51200
#define FV_STAGE 69632
#define FLM_SMEM 190464
#define VSTR 272

__global__ void __launch_bounds__(256, 1)
flash_f16_kernel(const __half* __restrict__ Qh,
                 const __half* __restrict__ Kh, const __half* __restrict__ Kl,
                 const __half* __restrict__ Vh, const __half* __restrict__ Vl,
                 __half* __restrict__ Zh)
{
    extern __shared__ char sm[];
    const uint32_t sb = smem_u32(sm);

    const int tid  = threadIdx.x;
    const int lane = tid & 31;
    const int wq   = tid >> 5;
    const int bh   = blockIdx.y;
    const int h    = bh & (H_ - 1);
    const int b_   = bh >> 4;
    const int q0   = blockIdx.x * 128;
    const int g    = lane >> 2;
    const int t4   = lane & 3;

    const float slope = exp2f(-0.5f * (float)(h + 1));
    const float NEG_INF = -__int_as_float(0x7f800000);

    auto issue_kv = [&](int st, int kt2) {
        const int k0 = kt2 * 128;
        const __half* kh = Kh + ((size_t)bh * N_ + k0) * R_;
        const __half* kl = Kl + ((size_t)bh * N_ + k0) * R_;
#pragma unroll
        for (int v = 0; v < 4; v++) {
            int idx = (v & 1) * 256 + tid;
            int row = idx >> 2, q = idx & 3;
            const __half* src = (v < 2 ? kh : kl) + (size_t)row * R_ + q * 8;
            uint32_t dst = sb + FK_BASE + st * FK_STAGE + (v < 2 ? 0 : 10240)
                         + (uint32_t)(row * 80 + q * 16);
            cp16(dst, src);
        }
        const __half* vh = Vh + ((size_t)bh * N_ + k0) * DK_;
        const __half* vl = Vl + ((size_t)bh * N_ + k0) * DK_;
#pragma unroll
        for (int v = 0; v < 16; v++) {
            int idx = (v & 7) * 256 + tid;
            int row = idx >> 4, q = idx & 15;
            const __half* src = (v < 8 ? vh : vl) + (size_t)row * DK_ + q * 8;
            uint32_t dst = sb + FV_BASE + st * FV_STAGE + (v < 8 ? 0 : 34816)
                         + (uint32_t)(row * VSTR + q * 16);
            cp16(dst, src);
        }
    };

    // Q load (one-time, plain fp16)
    {
        const __half* qg = Qh + ((size_t)bh * N_ + q0) * R_;
#pragma unroll
        for (int v = 0; v < 2; v++) {
            int idx = v * 256 + tid;
            int row = idx >> 2, q = idx & 3;
            cp16(sb + FQ + (uint32_t)(row * 80 + q * 16),
                 qg + (size_t)row * R_ + q * 8);
        }
    }
    CP_COMMIT();
    issue_kv(0, 0); CP_COMMIT();
    issue_kv(1, 1); CP_COMMIT();

    CP_WAITG(2);
    __syncthreads();

    uint32_t qf[2][4];
    {
        uint32_t qaddr = sb + FQ +
            (uint32_t)((wq * 16 + (lane & 15)) * 80 + (lane >> 4) * 16);
#pragma unroll
        for (int ks = 0; ks < 2; ks++)
            ldsm_x4(qf[ks], qaddr + ks * 32);
    }

    float o[16][4];
#pragma unroll
    for (int d = 0; d < 16; d++)
#pragma unroll
        for (int f = 0; f < 4; f++) o[d][f] = 0.f;
    float m_i[2] = {NEG_INF, NEG_INF};
    float l_i[2] = {0.f, 0.f};

    for (int kt = 0; kt < N_ / 128; kt++) {
        const int k0 = kt * 128;
        CP_WAITG(1);
        __syncthreads();
        const int st = kt & 1;

        // ---- S = Q (Kh + Kl)^T ----
        float s[16][4];
#pragma unroll
        for (int nb = 0; nb < 16; nb++)
#pragma unroll
            for (int f = 0; f < 4; f++) s[nb][f] = 0.f;

        {
            uint32_t baddr = sb + FK_BASE + st * FK_STAGE +
                (uint32_t)((lane & 7) * 80 + ((lane >> 3) & 1) * 16);
#pragma unroll
            for (int ks = 0; ks < 2; ks++) {
#pragma unroll
                for (int nb = 0; nb < 16; nb++) {
                    uint32_t bhh[2], bll[2];
                    uint32_t off = (uint32_t)(nb * 640 + ks * 32);
                    ldsm_x2(bhh, baddr + off);
                    ldsm_x2(bll, baddr + off + 10240);
                    mma_f16(s[nb], qf[ks], bhh);
                    mma_f16(s[nb], qf[ks], bll);
                }
            }
        }

        // ---- ALiBi + online softmax (registers) ----
#pragma unroll
        for (int nb = 0; nb < 16; nb++) {
#pragma unroll
            for (int f = 0; f < 4; f++) {
                int r = f >> 1, c = f & 1;
                int jg = k0 + nb * 8 + t4 * 2 + c;
                int ig = q0 + wq * 16 + g + r * 8;
                s[nb][f] -= slope * fmaxf((float)(jg - ig), 0.f);
            }
        }

        float alpha[2], mnew[2];
#pragma unroll
        for (int r = 0; r < 2; r++) {
            float tm = NEG_INF;
#pragma unroll
            for (int nb = 0; nb < 16; nb++) {
                tm = fmaxf(tm, s[nb][r * 2]);
                tm = fmaxf(tm, s[nb][r * 2 + 1]);
            }
            tm = fmaxf(tm, __shfl_xor_sync(0xffffffffu, tm, 1));
            tm = fmaxf(tm, __shfl_xor_sync(0xffffffffu, tm, 2));
            mnew[r]  = fmaxf(m_i[r], tm);
            alpha[r] = __expf(m_i[r] - mnew[r]);
            m_i[r]   = mnew[r];
        }

        float rsum[2] = {0.f, 0.f};
#pragma unroll
        for (int nb = 0; nb < 16; nb++) {
#pragma unroll
            for (int f = 0; f < 4; f++) {
                int r = f >> 1;
                float p = __expf(s[nb][f] - mnew[r]);
                s[nb][f] = p;
                rsum[r] += p;
            }
        }
#pragma unroll
        for (int r = 0; r < 2; r++) {
            rsum[r] += __shfl_xor_sync(0xffffffffu, rsum[r], 1);
            rsum[r] += __shfl_xor_sync(0xffffffffu, rsum[r], 2);
            l_i[r] = l_i[r] * alpha[r] + rsum[r];
        }
#pragma unroll
        for (int d = 0; d < 16; d++)
#pragma unroll
            for (int f = 0; f < 4; f++) o[d][f] *= alpha[f >> 1];

        // ---- O += P (Vh + Vl)  (P packed plain fp16 reg->reg) ----
        {
            uint32_t vaddr = sb + FV_BASE + st * FV_STAGE +
                (uint32_t)((lane & 15) * VSTR + (lane >> 4) * 16);
#pragma unroll
            for (int ks = 0; ks < 8; ks++) {
                uint32_t aP[4];
                aP[0] = packh2(s[2 * ks][0],     s[2 * ks][1]);
                aP[1] = packh2(s[2 * ks][2],     s[2 * ks][3]);
                aP[2] = packh2(s[2 * ks + 1][0], s[2 * ks + 1][1]);
                aP[3] = packh2(s[2 * ks + 1][2], s[2 * ks + 1][3]);
#pragma unroll
                for (int db = 0; db < 8; db++) {
                    uint32_t vh4[4], vl4[4];
                    uint32_t off = (uint32_t)(ks * 16 * VSTR + db * 32);
                    ldsm_x4_t(vh4, vaddr + off);
                    ldsm_x4_t(vl4, vaddr + off + 34816);
                    mma_f16(o[db * 2],     aP, vh4);
                    mma_f16(o[db * 2],     aP, vl4);
                    mma_f16(o[db * 2 + 1], aP, vh4 + 2);
                    mma_f16(o[db * 2 + 1], aP, vl4 + 2);
                }
            }
        }
        __syncthreads();
        if (kt + 2 < N_ / 128) { issue_kv(st, kt + 2); CP_COMMIT(); }
    }

    // ---- finalize: Z (plain fp16) = O / l ----
    float inv[2] = {1.f / l_i[0], 1.f / l_i[1]};
#pragma unroll
    for (int db = 0; db < 16; db++) {
#pragma unroll
        for (int r = 0; r < 2; r++) {
            int row = q0 + wq * 16 + g + r * 8;
            size_t zoff = ((size_t)b_ * N_ + row) * D_ + h * DK_ + db * 8 + t4 * 2;
            *(uint32_t*)(Zh + zoff) =
                packh2(o[db][r * 2] * inv[r], o[db][r * 2 + 1] * inv[r]);
        }
    }
}

// ---------------------------------------------------------------------------
// Host launcher (graph-capturable: kernel launches only)
// ---------------------------------------------------------------------------
extern "C" void kernel_launch(void* const* d_in, const int* in_sizes, int n_in,
                              void* d_out, int out_size)
{
    (void)in_sizes; (void)n_in; (void)out_size;
    const float* x     = (const float*)d_in[0];
    const float* Wq    = (const float*)d_in[1];
    const float* Wk    = (const float*)d_in[2];
    const float* Wv    = (const float*)d_in[3];
    const float* U     = (const float*)d_in[4];
    const float* Wproj = (const float*)d_in[5];
    float* out = (float*)d_out;

    __half *xh, *WUqh, *WUql, *WUkh, *WUkl, *Wvh, *Wvl, *Wph, *Wpl;
    __half *Qh, *Ql, *Kh, *Kl, *Vh, *Vl, *Zh;
    cudaGetSymbolAddress((void**)&xh,   g_xh);
    cudaGetSymbolAddress((void**)&WUqh, g_WUqh);
    cudaGetSymbolAddress((void**)&WUql, g_WUql);
    cudaGetSymbolAddress((void**)&WUkh, g_WUkh);
    cudaGetSymbolAddress((void**)&WUkl, g_WUkl);
    cudaGetSymbolAddress((void**)&Wvh,  g_Wvh);
    cudaGetSymbolAddress((void**)&Wvl,  g_Wvl);
    cudaGetSymbolAddress((void**)&Wph,  g_Wph);
    cudaGetSymbolAddress((void**)&Wpl,  g_Wpl);
    cudaGetSymbolAddress((void**)&Qh,   g_Qh);
    cudaGetSymbolAddress((void**)&Ql,   g_Ql);
    cudaGetSymbolAddress((void**)&Kh,   g_Kh);
    cudaGetSymbolAddress((void**)&Kl,   g_Kl);
    cudaGetSymbolAddress((void**)&Vh,   g_Vh);
    cudaGetSymbolAddress((void**)&Vl,   g_Vl);
    cudaGetSymbolAddress((void**)&Zh,   g_Zh);

    cudaFuncSetAttribute(gemm_f16x2<1, R_>,
                         cudaFuncAttributeMaxDynamicSharedMemorySize, GEMM_SMEM);
    cudaFuncSetAttribute(gemm_f16x2<1, DK_>,
                         cudaFuncAttributeMaxDynamicSharedMemorySize, GEMM_SMEM);
    cudaFuncSetAttribute(gemm_f16x2<0, 1>,
                         cudaFuncAttributeMaxDynamicSharedMemorySize, GEMM_SMEM);
    cudaFuncSetAttribute(flash_f16_kernel,
                         cudaFuncAttributeMaxDynamicSharedMemorySize, FLM_SMEM);

    const float qscale = rsqrtf((float)DK_);

    // 0) one-time conversions + U-folding
    cvt_f16_kernel<<<(M_ * D_ / 4) / 256, 256>>>(
        (const float4*)x, (uint2*)xh, M_ * D_ / 4);
    split_f16_kernel<<<(D_ * D_ / 4) / 256, 256>>>(
        (const float4*)Wv, (uint2*)Wvh, (uint2*)Wvl, D_ * D_ / 4);
    split_f16_kernel<<<(D_ * D_ / 4) / 256, 256>>>(
        (const float4*)Wproj, (uint2*)Wph, (uint2*)Wpl, D_ * D_ / 4);
    build_wu_kernel<<<dim3(D_ / 256, H_, 4), 256>>>(Wq, U, WUqh, WUql);
    build_wu_kernel<<<dim3(D_ / 256, H_, 4), 256>>>(Wk, U, WUkh, WUkl);

    // 1) Q = (x @ WUq^T) * 1/sqrt(dk) -> fp16 hi/lo [b,h,n,r] (lo unused)
    gemm_f16x2<1, R_><<<dim3(HR_ / 128, M_ / 128), 256, GEMM_SMEM>>>(
        xh, WUqh, WUql, nullptr, Qh, Ql, HR_, D_, qscale);
    // 2) K = x @ WUk^T -> fp16 hi/lo
    gemm_f16x2<1, R_><<<dim3(HR_ / 128, M_ / 128), 256, GEMM_SMEM>>>(
        xh, WUkh, WUkl, nullptr, Kh, Kl, HR_, D_, 1.0f);
    // 3) V = x @ Wv^T -> fp16 hi/lo [b,h,n,dk]
    gemm_f16x2<1, DK_><<<dim3(D_ / 128, M_ / 128), 256, GEMM_SMEM>>>(
        xh, Wvh, Wvl, nullptr, Vh, Vl, D_, D_, 1.0f);

    // 4) flash attention with ALiBi -> Z plain fp16 [b,n,d]
    flash_f16_kernel<<<dim3(N_ / 128, B_ * H_), 256, FLM_SMEM>>>(
        Qh, Kh, Kl, Vh, Vl, Zh);

    // 5) out = Z @ Wproj^T -> fp32
    gemm_f16x2<0, 1><<<dim3(D_ / 128, M_ / 128), 256, GEMM_SMEM>>>(
        Zh, Wph, Wpl, out, nullptr, nullptr, D_, D_, 1.0f);
}

// round 13
// speedup vs baseline: 1.8679x; 1.3154x over previous
#include <cuda_runtime.h>
#include <cuda_fp16.h>
#include <math.h>
#include <stdint.h>

// ---------------------------------------------------------------------------
// Problem constants (B=4, N=2048, D=2048, H=16, DK=128, R=32)
// ---------------------------------------------------------------------------
#define B_   4
#define N_   2048
#define D_   2048
#define H_   16
#define DK_  128
#define R_   32
#define M_   (B_ * N_)      // 8192
#define HR_  (H_ * R_)      // 512

// ---------------------------------------------------------------------------
// Device scratch
// ---------------------------------------------------------------------------
__device__ __half g_xh  [(size_t)M_ * D_];
__device__ __half g_WUqh[(size_t)HR_ * D_];
__device__ __half g_WUql[(size_t)HR_ * D_];   // written by build_wu, unused
__device__ __half g_WUkh[(size_t)HR_ * D_];
__device__ __half g_WUkl[(size_t)HR_ * D_];
__device__ __half g_Wvh [(size_t)D_ * D_];
__device__ __half g_Wvl [(size_t)D_ * D_];
__device__ __half g_Wph [(size_t)D_ * D_];
__device__ __half g_Qh  [(size_t)B_ * H_ * N_ * R_];
__device__ __half g_Kh  [(size_t)B_ * H_ * N_ * R_];
__device__ __half g_Kl  [(size_t)B_ * H_ * N_ * R_];
__device__ __half g_Vh  [(size_t)B_ * H_ * N_ * DK_];
__device__ __half g_Zh  [(size_t)M_ * D_];

// ---------------------------------------------------------------------------
// PTX wrappers (sm_80-era, valid on plain sm_103 target)
// ---------------------------------------------------------------------------
__device__ __forceinline__ uint32_t smem_u32(const void* p) {
    uint32_t a;
    asm("{ .reg .u64 t; cvta.to.shared.u64 t, %1; cvt.u32.u64 %0, t; }"
        : "=r"(a) : "l"(p));
    return a;
}
__device__ __forceinline__ void ldsm_x4(uint32_t* r, uint32_t addr) {
    asm volatile("ldmatrix.sync.aligned.m8n8.x4.shared.b16 {%0,%1,%2,%3}, [%4];"
                 : "=r"(r[0]), "=r"(r[1]), "=r"(r[2]), "=r"(r[3]) : "r"(addr));
}
__device__ __forceinline__ void ldsm_x2(uint32_t* r, uint32_t addr) {
    asm volatile("ldmatrix.sync.aligned.m8n8.x2.shared.b16 {%0,%1}, [%2];"
                 : "=r"(r[0]), "=r"(r[1]) : "r"(addr));
}
__device__ __forceinline__ void ldsm_x4_t(uint32_t* r, uint32_t addr) {
    asm volatile("ldmatrix.sync.aligned.m8n8.x4.trans.shared.b16 {%0,%1,%2,%3}, [%4];"
                 : "=r"(r[0]), "=r"(r[1]), "=r"(r[2]), "=r"(r[3]) : "r"(addr));
}
__device__ __forceinline__ void mma_f16(float* d, const uint32_t* a, const uint32_t* b) {
    asm volatile(
        "mma.sync.aligned.m16n8k16.row.col.f32.f16.f16.f32 "
        "{%0,%1,%2,%3}, {%4,%5,%6,%7}, {%8,%9}, {%0,%1,%2,%3};"
        : "+f"(d[0]), "+f"(d[1]), "+f"(d[2]), "+f"(d[3])
        : "r"(a[0]), "r"(a[1]), "r"(a[2]), "r"(a[3]), "r"(b[0]), "r"(b[1]));
}
__device__ __forceinline__ void cp16(uint32_t dst, const void* src) {
    asm volatile("cp.async.cg.shared.global [%0], [%1], 16;"
                 :: "r"(dst), "l"(src) : "memory");
}
#define CP_COMMIT() asm volatile("cp.async.commit_group;" ::: "memory")
#define CP_WAITG(n) asm volatile("cp.async.wait_group %0;" :: "n"(n) : "memory")

__device__ __forceinline__ uint32_t packh2(float x, float y) {
    __half2 hh = __floats2half2_rn(x, y);
    return *reinterpret_cast<uint32_t*>(&hh);
}
__device__ __forceinline__ void split2h(float x, __half& h, __half& l) {
    h = __float2half(x);
    l = __float2half(x - __half2float(h));
}
__device__ __forceinline__ uint32_t packh(__half a, __half b) {
    return (uint32_t)__half_as_ushort(a) | ((uint32_t)__half_as_ushort(b) << 16);
}

// ---------------------------------------------------------------------------
// Prep kernels
// ---------------------------------------------------------------------------
__global__ void cvt_f16_kernel(const float4* __restrict__ in,
                               uint2* __restrict__ h, int n4)
{
    int i = blockIdx.x * 256 + threadIdx.x;
    if (i >= n4) return;
    float4 v = in[i];
    h[i] = make_uint2(packh2(v.x, v.y), packh2(v.z, v.w));
}

__global__ void split_f16_kernel(const float4* __restrict__ in,
                                 uint2* __restrict__ hi, uint2* __restrict__ lo, int n4)
{
    int i = blockIdx.x * 256 + threadIdx.x;
    if (i >= n4) return;
    float4 v = in[i];
    __half h0, h1, h2, h3, l0, l1, l2, l3;
    split2h(v.x, h0, l0); split2h(v.y, h1, l1);
    split2h(v.z, h2, l2); split2h(v.w, h3, l3);
    hi[i] = make_uint2(packh(h0, h1), packh(h2, h3));
    lo[i] = make_uint2(packh(l0, l1), packh(l2, l3));
}

__global__ void build_wu_kernel(const float* __restrict__ W,
                                const float* __restrict__ U,
                                __half* __restrict__ WUh,
                                __half* __restrict__ WUl)
{
    __shared__ float Us[128][8];
    const int tid = threadIdx.x;
    const int d   = blockIdx.x * 256 + tid;
    const int h   = blockIdx.y;
    const int rg  = blockIdx.z;

    for (int i = tid; i < 128 * 8; i += 256) {
        int dk = i >> 3, j = i & 7;
        Us[dk][j] = U[dk * R_ + rg * 8 + j];
    }
    __syncthreads();

    const float* wcol = W + (size_t)h * DK_ * D_ + d;
    float acc[8];
#pragma unroll
    for (int j = 0; j < 8; j++) acc[j] = 0.f;
#pragma unroll 4
    for (int dk = 0; dk < DK_; dk++) {
        float w = wcol[(size_t)dk * D_];
#pragma unroll
        for (int j = 0; j < 8; j++) acc[j] = fmaf(w, Us[dk][j], acc[j]);
    }
#pragma unroll
    for (int j = 0; j < 8; j++) {
        __half hh, ll;
        split2h(acc[j], hh, ll);
        size_t off = (size_t)(h * 32 + rg * 8 + j) * D_ + d;
        WUh[off] = hh;
        WUl[off] = ll;
    }
}

// ---------------------------------------------------------------------------
// HMMA fp16 GEMM: C = A * B^T, A plain fp16; B 1-pass (Bh) or 2-pass (Bh+Bl).
// CTA 128x128, BK=32, 8 warps (2x4), warp tile 64x32, 2-stage cp.async.
// MODE 0: fp32 C[m*NN+n]
// MODE 1: fp16 hi/lo head-split (scaled)
// MODE 2: fp16 plain head-split (scaled)
// ---------------------------------------------------------------------------
template <int MODE, int SPLIT, int BPASS>
__global__ void __launch_bounds__(256, 2)
gemm_f16(const __half* __restrict__ A_,
         const __half* __restrict__ Bh_,
         const __half* __restrict__ Bl_,
         float* __restrict__ Cf,
         __half* __restrict__ Ch,
         __half* __restrict__ Cl,
         int NN, int K, float scale)
{
    constexpr int NPARTS = 1 + BPASS;            // A, Bh, [Bl]
    constexpr uint32_t SGS = NPARTS * 10240u;    // stage size

    extern __shared__ char sm[];
    const uint32_t sb = smem_u32(sm);

    const int tid  = threadIdx.x;
    const int lane = tid & 31;
    const int wid  = tid >> 5;
    const int wm   = wid & 1;
    const int wn   = wid >> 1;
    const int m0   = blockIdx.y * 128;
    const int n0   = blockIdx.x * 128;

    const __half* bases[3] = {
        A_  + (size_t)m0 * K,
        Bh_ + (size_t)n0 * K,
        (BPASS == 2) ? (Bl_ + (size_t)n0 * K) : nullptr };

    auto issue = [&](int st, int it) {
        const uint32_t stb = sb + (uint32_t)st * SGS;
#pragma unroll
        for (int v = 0; v < NPARTS * 2; v++) {
            const int p = v >> 1;                  // compile-time part index
            int rq = (v & 1) * 256 + tid;          // 0..511
            int r  = rq >> 2, q = rq & 3;
            const __half* src = bases[p] + (size_t)r * K + it * 32 + q * 8;
            cp16(stb + (uint32_t)(p * 10240 + r * 80 + q * 16), src);
        }
    };

    const int niter = K / 32;
    issue(0, 0); CP_COMMIT();
    issue(1, 1); CP_COMMIT();

    float acc[4][4][4];
#pragma unroll
    for (int mi = 0; mi < 4; mi++)
#pragma unroll
        for (int ni = 0; ni < 4; ni++)
#pragma unroll
            for (int f = 0; f < 4; f++) acc[mi][ni][f] = 0.f;

    const uint32_t a_off =
        (uint32_t)((wm * 64 + (lane & 15)) * 80 + (lane >> 4) * 16);
    const uint32_t b_off = 10240u +
        (uint32_t)((wn * 32 + (lane & 7)) * 80 + ((lane >> 3) & 1) * 16);

    for (int it = 0; it < niter; ++it) {
        CP_WAITG(1);
        __syncthreads();
        const uint32_t stb = sb + (uint32_t)(it & 1) * SGS;
        const uint32_t a_addr = stb + a_off;
        const uint32_t b_addr = stb + b_off;

#pragma unroll
        for (int ks = 0; ks < 2; ks++) {
            uint32_t ah[4][4];
#pragma unroll
            for (int mi = 0; mi < 4; mi++)
                ldsm_x4(ah[mi], a_addr + (uint32_t)(mi * 1280 + ks * 32));
#pragma unroll
            for (int ni = 0; ni < 4; ni++) {
                uint32_t bh[2], bl[2];
                uint32_t off = (uint32_t)(ni * 640 + ks * 32);
                ldsm_x2(bh, b_addr + off);
                if (BPASS == 2) ldsm_x2(bl, b_addr + off + 10240);
#pragma unroll
                for (int mi = 0; mi < 4; mi++) {
                    mma_f16(acc[mi][ni], ah[mi], bh);
                    if (BPASS == 2) mma_f16(acc[mi][ni], ah[mi], bl);
                }
            }
        }
        __syncthreads();
        if (it + 2 < niter) { issue(it & 1, it + 2); CP_COMMIT(); }
    }

    // epilogue
    const int g  = lane >> 2;
    const int c2 = (lane & 3) * 2;
#pragma unroll
    for (int mi = 0; mi < 4; mi++) {
#pragma unroll
        for (int ni = 0; ni < 4; ni++) {
            int m = m0 + wm * 64 + mi * 16 + g;
            int n = n0 + wn * 32 + ni * 8 + c2;
#pragma unroll
            for (int half_ = 0; half_ < 2; half_++) {
                int mm = m + half_ * 8;
                float v0 = acc[mi][ni][half_ * 2];
                float v1 = acc[mi][ni][half_ * 2 + 1];
                if (MODE == 0) {
                    *(float2*)(Cf + (size_t)mm * NN + n) = make_float2(v0, v1);
                } else {
                    int b_ = mm >> 11;
                    int t  = mm & (N_ - 1);
                    int h  = n / SPLIT;
                    int j  = n % SPLIT;
                    size_t off = (((size_t)(b_ * H_ + h)) * N_ + t) * SPLIT + j;
                    if (MODE == 1) {
                        __half h0, l0, h1, l1;
                        split2h(v0 * scale, h0, l0);
                        split2h(v1 * scale, h1, l1);
                        *(uint32_t*)(Ch + off) = packh(h0, h1);
                        *(uint32_t*)(Cl + off) = packh(l0, l1);
                    } else {
                        *(uint32_t*)(Ch + off) = packh2(v0 * scale, v1 * scale);
                    }
                }
            }
        }
    }
}

// ---------------------------------------------------------------------------
// HMMA flash attention: Q plain fp16 (regs), K 2-pass hi/lo, V plain 1-pass.
// smem: Q 10240 | K stages 2x20480 | V stages 2x34816 = 120832 B
// ---------------------------------------------------------------------------
#define FQ 0
#define FK_BASE 10240
#define FK_STAGE 20480
#define FV_BASE 51200
#define FV_STAGE 34816
#define FLM_SMEM 120832
#define VSTR 272

__global__ void __launch_bounds__(256, 1)
flash_f16_kernel(const __half* __restrict__ Qh,
                 const __half* __restrict__ Kh, const __half* __restrict__ Kl,
                 const __half* __restrict__ Vh,
                 __half* __restrict__ Zh)
{
    extern __shared__ char sm[];
    const uint32_t sb = smem_u32(sm);

    const int tid  = threadIdx.x;
    const int lane = tid & 31;
    const int wq   = tid >> 5;
    const int bh   = blockIdx.y;
    const int h    = bh & (H_ - 1);
    const int b_   = bh >> 4;
    const int q0   = blockIdx.x * 128;
    const int g    = lane >> 2;
    const int t4   = lane & 3;

    const float slope = exp2f(-0.5f * (float)(h + 1));
    const float NEG_INF = -__int_as_float(0x7f800000);

    auto issue_kv = [&](int st, int kt2) {
        const int k0 = kt2 * 128;
        const __half* kh = Kh + ((size_t)bh * N_ + k0) * R_;
        const __half* kl = Kl + ((size_t)bh * N_ + k0) * R_;
#pragma unroll
        for (int v = 0; v < 4; v++) {
            int idx = (v & 1) * 256 + tid;
            int row = idx >> 2, q = idx & 3;
            const __half* src = (v < 2 ? kh : kl) + (size_t)row * R_ + q * 8;
            uint32_t dst = sb + FK_BASE + st * FK_STAGE + (v < 2 ? 0 : 10240)
                         + (uint32_t)(row * 80 + q * 16);
            cp16(dst, src);
        }
        const __half* vh = Vh + ((size_t)bh * N_ + k0) * DK_;
#pragma unroll
        for (int v = 0; v < 8; v++) {
            int idx = v * 256 + tid;
            int row = idx >> 4, q = idx & 15;
            uint32_t dst = sb + FV_BASE + st * FV_STAGE
                         + (uint32_t)(row * VSTR + q * 16);
            cp16(dst, vh + (size_t)row * DK_ + q * 8);
        }
    };

    // Q load (one-time, plain fp16)
    {
        const __half* qg = Qh + ((size_t)bh * N_ + q0) * R_;
#pragma unroll
        for (int v = 0; v < 2; v++) {
            int idx = v * 256 + tid;
            int row = idx >> 2, q = idx & 3;
            cp16(sb + FQ + (uint32_t)(row * 80 + q * 16),
                 qg + (size_t)row * R_ + q * 8);
        }
    }
    CP_COMMIT();
    issue_kv(0, 0); CP_COMMIT();
    issue_kv(1, 1); CP_COMMIT();

    CP_WAITG(2);
    __syncthreads();

    uint32_t qf[2][4];
    {
        uint32_t qaddr = sb + FQ +
            (uint32_t)((wq * 16 + (lane & 15)) * 80 + (lane >> 4) * 16);
#pragma unroll
        for (int ks = 0; ks < 2; ks++)
            ldsm_x4(qf[ks], qaddr + ks * 32);
    }

    float o[16][4];
#pragma unroll
    for (int d = 0; d < 16; d++)
#pragma unroll
        for (int f = 0; f < 4; f++) o[d][f] = 0.f;
    float m_i[2] = {NEG_INF, NEG_INF};
    float l_i[2] = {0.f, 0.f};

    for (int kt = 0; kt < N_ / 128; kt++) {
        const int k0 = kt * 128;
        CP_WAITG(1);
        __syncthreads();
        const int st = kt & 1;

        // ---- S = Q (Kh + Kl)^T ----
        float s[16][4];
#pragma unroll
        for (int nb = 0; nb < 16; nb++)
#pragma unroll
            for (int f = 0; f < 4; f++) s[nb][f] = 0.f;

        {
            uint32_t baddr = sb + FK_BASE + st * FK_STAGE +
                (uint32_t)((lane & 7) * 80 + ((lane >> 3) & 1) * 16);
#pragma unroll
            for (int ks = 0; ks < 2; ks++) {
#pragma unroll
                for (int nb = 0; nb < 16; nb++) {
                    uint32_t bhh[2], bll[2];
                    uint32_t off = (uint32_t)(nb * 640 + ks * 32);
                    ldsm_x2(bhh, baddr + off);
                    ldsm_x2(bll, baddr + off + 10240);
                    mma_f16(s[nb], qf[ks], bhh);
                    mma_f16(s[nb], qf[ks], bll);
                }
            }
        }

        // ---- ALiBi + online softmax (registers) ----
#pragma unroll
        for (int nb = 0; nb < 16; nb++) {
#pragma unroll
            for (int f = 0; f < 4; f++) {
                int r = f >> 1, c = f & 1;
                int jg = k0 + nb * 8 + t4 * 2 + c;
                int ig = q0 + wq * 16 + g + r * 8;
                s[nb][f] -= slope * fmaxf((float)(jg - ig), 0.f);
            }
        }

        float alpha[2], mnew[2];
#pragma unroll
        for (int r = 0; r < 2; r++) {
            float tm = NEG_INF;
#pragma unroll
            for (int nb = 0; nb < 16; nb++) {
                tm = fmaxf(tm, s[nb][r * 2]);
                tm = fmaxf(tm, s[nb][r * 2 + 1]);
            }
            tm = fmaxf(tm, __shfl_xor_sync(0xffffffffu, tm, 1));
            tm = fmaxf(tm, __shfl_xor_sync(0xffffffffu, tm, 2));
            mnew[r]  = fmaxf(m_i[r], tm);
            alpha[r] = __expf(m_i[r] - mnew[r]);
            m_i[r]   = mnew[r];
        }

        float rsum[2] = {0.f, 0.f};
#pragma unroll
        for (int nb = 0; nb < 16; nb++) {
#pragma unroll
            for (int f = 0; f < 4; f++) {
                int r = f >> 1;
                float p = __expf(s[nb][f] - mnew[r]);
                s[nb][f] = p;
                rsum[r] += p;
            }
        }
#pragma unroll
        for (int r = 0; r < 2; r++) {
            rsum[r] += __shfl_xor_sync(0xffffffffu, rsum[r], 1);
            rsum[r] += __shfl_xor_sync(0xffffffffu, rsum[r], 2);
            l_i[r] = l_i[r] * alpha[r] + rsum[r];
        }
#pragma unroll
        for (int d = 0; d < 16; d++)
#pragma unroll
            for (int f = 0; f < 4; f++) o[d][f] *= alpha[f >> 1];

        // ---- O += P V (single-pass V, plain fp16) ----
        {
            uint32_t vaddr = sb + FV_BASE + st * FV_STAGE +
                (uint32_t)((lane & 15) * VSTR + (lane >> 4) * 16);
#pragma unroll
            for (int ks = 0; ks < 8; ks++) {
                uint32_t aP[4];
                aP[0] = packh2(s[2 * ks][0],     s[2 * ks][1]);
                aP[1] = packh2(s[2 * ks][2],     s[2 * ks][3]);
                aP[2] = packh2(s[2 * ks + 1][0], s[2 * ks + 1][1]);
                aP[3] = packh2(s[2 * ks + 1][2], s[2 * ks + 1][3]);
#pragma unroll
                for (int db = 0; db < 8; db++) {
                    uint32_t vh4[4];
                    ldsm_x4_t(vh4, vaddr + (uint32_t)(ks * 16 * VSTR + db * 32));
                    mma_f16(o[db * 2],     aP, vh4);
                    mma_f16(o[db * 2 + 1], aP, vh4 + 2);
                }
            }
        }
        __syncthreads();
        if (kt + 2 < N_ / 128) { issue_kv(st, kt + 2); CP_COMMIT(); }
    }

    // ---- finalize: Z (plain fp16) = O / l ----
    float inv[2] = {1.f / l_i[0], 1.f / l_i[1]};
#pragma unroll
    for (int db = 0; db < 16; db++) {
#pragma unroll
        for (int r = 0; r < 2; r++) {
            int row = q0 + wq * 16 + g + r * 8;
            size_t zoff = ((size_t)b_ * N_ + row) * D_ + h * DK_ + db * 8 + t4 * 2;
            *(uint32_t*)(Zh + zoff) =
                packh2(o[db][r * 2] * inv[r], o[db][r * 2 + 1] * inv[r]);
        }
    }
}

// ---------------------------------------------------------------------------
// Host launcher (graph-capturable: kernel launches only)
// ---------------------------------------------------------------------------
extern "C" void kernel_launch(void* const* d_in, const int* in_sizes, int n_in,
                              void* d_out, int out_size)
{
    (void)in_sizes; (void)n_in; (void)out_size;
    const float* x     = (const float*)d_in[0];
    const float* Wq    = (const float*)d_in[1];
    const float* Wk    = (const float*)d_in[2];
    const float* Wv    = (const float*)d_in[3];
    const float* U     = (const float*)d_in[4];
    const float* Wproj = (const float*)d_in[5];
    float* out = (float*)d_out;

    __half *xh, *WUqh, *WUql, *WUkh, *WUkl, *Wvh, *Wvl, *Wph;
    __half *Qh, *Kh, *Kl, *Vh, *Zh;
    cudaGetSymbolAddress((void**)&xh,   g_xh);
    cudaGetSymbolAddress((void**)&WUqh, g_WUqh);
    cudaGetSymbolAddress((void**)&WUql, g_WUql);
    cudaGetSymbolAddress((void**)&WUkh, g_WUkh);
    cudaGetSymbolAddress((void**)&WUkl, g_WUkl);
    cudaGetSymbolAddress((void**)&Wvh,  g_Wvh);
    cudaGetSymbolAddress((void**)&Wvl,  g_Wvl);
    cudaGetSymbolAddress((void**)&Wph,  g_Wph);
    cudaGetSymbolAddress((void**)&Qh,   g_Qh);
    cudaGetSymbolAddress((void**)&Kh,   g_Kh);
    cudaGetSymbolAddress((void**)&Kl,   g_Kl);
    cudaGetSymbolAddress((void**)&Vh,   g_Vh);
    cudaGetSymbolAddress((void**)&Zh,   g_Zh);

    cudaFuncSetAttribute(gemm_f16<2, R_, 1>,
                         cudaFuncAttributeMaxDynamicSharedMemorySize, 2 * 2 * 10240);
    cudaFuncSetAttribute(gemm_f16<1, R_, 2>,
                         cudaFuncAttributeMaxDynamicSharedMemorySize, 2 * 3 * 10240);
    cudaFuncSetAttribute(gemm_f16<2, DK_, 2>,
                         cudaFuncAttributeMaxDynamicSharedMemorySize, 2 * 3 * 10240);
    cudaFuncSetAttribute(gemm_f16<0, 1, 1>,
                         cudaFuncAttributeMaxDynamicSharedMemorySize, 2 * 2 * 10240);
    cudaFuncSetAttribute(flash_f16_kernel,
                         cudaFuncAttributeMaxDynamicSharedMemorySize, FLM_SMEM);

    const float qscale = rsqrtf((float)DK_);

    // 0) one-time conversions + U-folding
    cvt_f16_kernel<<<(M_ * D_ / 4) / 256, 256>>>(
        (const float4*)x, (uint2*)xh, M_ * D_ / 4);
    split_f16_kernel<<<(D_ * D_ / 4) / 256, 256>>>(
        (const float4*)Wv, (uint2*)Wvh, (uint2*)Wvl, D_ * D_ / 4);
    cvt_f16_kernel<<<(D_ * D_ / 4) / 256, 256>>>(
        (const float4*)Wproj, (uint2*)Wph, D_ * D_ / 4);
    build_wu_kernel<<<dim3(D_ / 256, H_, 4), 256>>>(Wq, U, WUqh, WUql);
    build_wu_kernel<<<dim3(D_ / 256, H_, 4), 256>>>(Wk, U, WUkh, WUkl);

    // 1) Q = (x @ WUq^T) * 1/sqrt(dk) -> plain fp16 [b,h,n,r]  (1-pass B)
    gemm_f16<2, R_, 1><<<dim3(HR_ / 128, M_ / 128), 256, 2 * 2 * 10240>>>(
        xh, WUqh, nullptr, nullptr, Qh, nullptr, HR_, D_, qscale);
    // 2) K = x @ WUk^T -> fp16 hi/lo  (2-pass B: logit accuracy)
    gemm_f16<1, R_, 2><<<dim3(HR_ / 128, M_ / 128), 256, 2 * 3 * 10240>>>(
        xh, WUkh, WUkl, nullptr, Kh, Kl, HR_, D_, 1.0f);
    // 3) V = x @ Wv^T -> plain fp16 [b,h,n,dk]  (2-pass B, plain out)
    gemm_f16<2, DK_, 2><<<dim3(D_ / 128, M_ / 128), 256, 2 * 3 * 10240>>>(
        xh, Wvh, Wvl, nullptr, Vh, nullptr, D_, D_, 1.0f);

    // 4) flash attention with ALiBi -> Z plain fp16 [b,n,d]
    flash_f16_kernel<<<dim3(N_ / 128, B_ * H_), 256, FLM_SMEM>>>(
        Qh, Kh, Kl, Vh, Zh);

    // 5) out = Z @ Wproj^T -> fp32  (1-pass B)
    gemm_f16<0, 1, 1><<<dim3(D_ / 128, M_ / 128), 256, 2 * 2 * 10240>>>(
        Zh, Wph, nullptr, out, nullptr, nullptr, D_, D_, 1.0f);
}

// round 14
// speedup vs baseline: 2.4368x; 1.3046x over previous
#include <cuda_runtime.h>
#include <cuda_fp16.h>
#include <math.h>
#include <stdint.h>

// ---------------------------------------------------------------------------
// Problem constants (B=4, N=2048, D=2048, H=16, DK=128, R=32)
// ---------------------------------------------------------------------------
#define B_   4
#define N_   2048
#define D_   2048
#define H_   16
#define DK_  128
#define R_   32
#define M_   (B_ * N_)      // 8192
#define HR_  (H_ * R_)      // 512

// ---------------------------------------------------------------------------
// Device scratch (all plain fp16)
// ---------------------------------------------------------------------------
__device__ __half g_xh  [(size_t)M_ * D_];
__device__ __half g_WUqh[(size_t)HR_ * D_];
__device__ __half g_WUkh[(size_t)HR_ * D_];
__device__ __half g_Wvh [(size_t)D_ * D_];
__device__ __half g_Wph [(size_t)D_ * D_];
__device__ __half g_Qh  [(size_t)B_ * H_ * N_ * R_];
__device__ __half g_Kh  [(size_t)B_ * H_ * N_ * R_];
__device__ __half g_Vh  [(size_t)B_ * H_ * N_ * DK_];
__device__ __half g_Zh  [(size_t)M_ * D_];

// ---------------------------------------------------------------------------
// PTX wrappers (sm_80-era, valid on plain sm_103 target)
// ---------------------------------------------------------------------------
__device__ __forceinline__ uint32_t smem_u32(const void* p) {
    uint32_t a;
    asm("{ .reg .u64 t; cvta.to.shared.u64 t, %1; cvt.u32.u64 %0, t; }"
        : "=r"(a) : "l"(p));
    return a;
}
__device__ __forceinline__ void ldsm_x4(uint32_t* r, uint32_t addr) {
    asm volatile("ldmatrix.sync.aligned.m8n8.x4.shared.b16 {%0,%1,%2,%3}, [%4];"
                 : "=r"(r[0]), "=r"(r[1]), "=r"(r[2]), "=r"(r[3]) : "r"(addr));
}
__device__ __forceinline__ void ldsm_x2(uint32_t* r, uint32_t addr) {
    asm volatile("ldmatrix.sync.aligned.m8n8.x2.shared.b16 {%0,%1}, [%2];"
                 : "=r"(r[0]), "=r"(r[1]) : "r"(addr));
}
__device__ __forceinline__ void ldsm_x4_t(uint32_t* r, uint32_t addr) {
    asm volatile("ldmatrix.sync.aligned.m8n8.x4.trans.shared.b16 {%0,%1,%2,%3}, [%4];"
                 : "=r"(r[0]), "=r"(r[1]), "=r"(r[2]), "=r"(r[3]) : "r"(addr));
}
__device__ __forceinline__ void mma_f16(float* d, const uint32_t* a, const uint32_t* b) {
    asm volatile(
        "mma.sync.aligned.m16n8k16.row.col.f32.f16.f16.f32 "
        "{%0,%1,%2,%3}, {%4,%5,%6,%7}, {%8,%9}, {%0,%1,%2,%3};"
        : "+f"(d[0]), "+f"(d[1]), "+f"(d[2]), "+f"(d[3])
        : "r"(a[0]), "r"(a[1]), "r"(a[2]), "r"(a[3]), "r"(b[0]), "r"(b[1]));
}
__device__ __forceinline__ void cp16(uint32_t dst, const void* src) {
    asm volatile("cp.async.cg.shared.global [%0], [%1], 16;"
                 :: "r"(dst), "l"(src) : "memory");
}
#define CP_COMMIT() asm volatile("cp.async.commit_group;" ::: "memory")
#define CP_WAITG(n) asm volatile("cp.async.wait_group %0;" :: "n"(n) : "memory")

__device__ __forceinline__ uint32_t packh2(float x, float y) {
    __half2 hh = __floats2half2_rn(x, y);
    return *reinterpret_cast<uint32_t*>(&hh);
}

// ---------------------------------------------------------------------------
// Prep kernels
// ---------------------------------------------------------------------------
__global__ void cvt_f16_kernel(const float4* __restrict__ in,
                               uint2* __restrict__ h, int n4)
{
    int i = blockIdx.x * 256 + threadIdx.x;
    if (i >= n4) return;
    float4 v = in[i];
    h[i] = make_uint2(packh2(v.x, v.y), packh2(v.z, v.w));
}

// WU[h*32 + r, d] = sum_dk W[h*128+dk, d] * U[dk, r] -> plain fp16
__global__ void build_wu_kernel(const float* __restrict__ W,
                                const float* __restrict__ U,
                                __half* __restrict__ WUh)
{
    __shared__ float Us[128][8];
    const int tid = threadIdx.x;
    const int d   = blockIdx.x * 256 + tid;
    const int h   = blockIdx.y;
    const int rg  = blockIdx.z;

    for (int i = tid; i < 128 * 8; i += 256) {
        int dk = i >> 3, j = i & 7;
        Us[dk][j] = U[dk * R_ + rg * 8 + j];
    }
    __syncthreads();

    const float* wcol = W + (size_t)h * DK_ * D_ + d;
    float acc[8];
#pragma unroll
    for (int j = 0; j < 8; j++) acc[j] = 0.f;
#pragma unroll 4
    for (int dk = 0; dk < DK_; dk++) {
        float w = wcol[(size_t)dk * D_];
#pragma unroll
        for (int j = 0; j < 8; j++) acc[j] = fmaf(w, Us[dk][j], acc[j]);
    }
#pragma unroll
    for (int j = 0; j < 8; j++) {
        size_t off = (size_t)(h * 32 + rg * 8 + j) * D_ + d;
        WUh[off] = __float2half(acc[j]);
    }
}

// ---------------------------------------------------------------------------
// HMMA fp16 GEMM (single-pass): C = A * B^T, both plain fp16.
// CTA 128x128, BK=32, 8 warps (2x4), warp tile 64x32, 2-stage cp.async.
// smem/stage: A@0, B@10240 (rows padded to 80B); 2 stages = 40960 B.
// MODE 0: fp32 C[m*NN+n]
// MODE 2: fp16 plain head-split (scaled)
// ---------------------------------------------------------------------------
#define SGS 20480u
#define GEMM_SMEM (2 * 20480)

template <int MODE, int SPLIT>
__global__ void __launch_bounds__(256, 2)
gemm_f16(const __half* __restrict__ A_,
         const __half* __restrict__ B_x,
         float* __restrict__ Cf,
         __half* __restrict__ Ch,
         int NN, int K, float scale)
{
    extern __shared__ char sm[];
    const uint32_t sb = smem_u32(sm);

    const int tid  = threadIdx.x;
    const int lane = tid & 31;
    const int wid  = tid >> 5;
    const int wm   = wid & 1;
    const int wn   = wid >> 1;
    const int m0   = blockIdx.y * 128;
    const int n0   = blockIdx.x * 128;

    const __half* bases[2] = { A_ + (size_t)m0 * K, B_x + (size_t)n0 * K };

    auto issue = [&](int st, int it) {
        const uint32_t stb = sb + (uint32_t)st * SGS;
#pragma unroll
        for (int v = 0; v < 4; v++) {
            const int p = v >> 1;
            int rq = (v & 1) * 256 + tid;          // 0..511
            int r  = rq >> 2, q = rq & 3;
            const __half* src = bases[p] + (size_t)r * K + it * 32 + q * 8;
            cp16(stb + (uint32_t)(p * 10240 + r * 80 + q * 16), src);
        }
    };

    const int niter = K / 32;
    issue(0, 0); CP_COMMIT();
    issue(1, 1); CP_COMMIT();

    float acc[4][4][4];
#pragma unroll
    for (int mi = 0; mi < 4; mi++)
#pragma unroll
        for (int ni = 0; ni < 4; ni++)
#pragma unroll
            for (int f = 0; f < 4; f++) acc[mi][ni][f] = 0.f;

    const uint32_t a_off =
        (uint32_t)((wm * 64 + (lane & 15)) * 80 + (lane >> 4) * 16);
    const uint32_t b_off = 10240u +
        (uint32_t)((wn * 32 + (lane & 7)) * 80 + ((lane >> 3) & 1) * 16);

    for (int it = 0; it < niter; ++it) {
        CP_WAITG(1);
        __syncthreads();
        const uint32_t stb = sb + (uint32_t)(it & 1) * SGS;
        const uint32_t a_addr = stb + a_off;
        const uint32_t b_addr = stb + b_off;

#pragma unroll
        for (int ks = 0; ks < 2; ks++) {
            uint32_t ah[4][4];
#pragma unroll
            for (int mi = 0; mi < 4; mi++)
                ldsm_x4(ah[mi], a_addr + (uint32_t)(mi * 1280 + ks * 32));
#pragma unroll
            for (int ni = 0; ni < 4; ni++) {
                uint32_t bh[2];
                ldsm_x2(bh, b_addr + (uint32_t)(ni * 640 + ks * 32));
#pragma unroll
                for (int mi = 0; mi < 4; mi++)
                    mma_f16(acc[mi][ni], ah[mi], bh);
            }
        }
        __syncthreads();
        if (it + 2 < niter) { issue(it & 1, it + 2); CP_COMMIT(); }
    }

    // epilogue
    const int g  = lane >> 2;
    const int c2 = (lane & 3) * 2;
#pragma unroll
    for (int mi = 0; mi < 4; mi++) {
#pragma unroll
        for (int ni = 0; ni < 4; ni++) {
            int m = m0 + wm * 64 + mi * 16 + g;
            int n = n0 + wn * 32 + ni * 8 + c2;
#pragma unroll
            for (int half_ = 0; half_ < 2; half_++) {
                int mm = m + half_ * 8;
                float v0 = acc[mi][ni][half_ * 2];
                float v1 = acc[mi][ni][half_ * 2 + 1];
                if (MODE == 0) {
                    *(float2*)(Cf + (size_t)mm * NN + n) = make_float2(v0, v1);
                } else {
                    int b_ = mm >> 11;
                    int t  = mm & (N_ - 1);
                    int h  = n / SPLIT;
                    int j  = n % SPLIT;
                    size_t off = (((size_t)(b_ * H_ + h)) * N_ + t) * SPLIT + j;
                    *(uint32_t*)(Ch + off) = packh2(v0 * scale, v1 * scale);
                }
            }
        }
    }
}

// ---------------------------------------------------------------------------
// HMMA flash attention: all operands plain fp16, single-pass S and PV.
// smem: Q 10240 | K stages 2x10240 | V stages 2x34816 = 100352 B
// ---------------------------------------------------------------------------
#define FQ 0
#define FK_BASE 10240
#define FK_STAGE 10240
#define FV_BASE 30720
#define FV_STAGE 34816
#define FLM_SMEM 100352
#define VSTR 272

__global__ void __launch_bounds__(256, 1)
flash_f16_kernel(const __half* __restrict__ Qh,
                 const __half* __restrict__ Kh,
                 const __half* __restrict__ Vh,
                 __half* __restrict__ Zh)
{
    extern __shared__ char sm[];
    const uint32_t sb = smem_u32(sm);

    const int tid  = threadIdx.x;
    const int lane = tid & 31;
    const int wq   = tid >> 5;
    const int bh   = blockIdx.y;
    const int h    = bh & (H_ - 1);
    const int b_   = bh >> 4;
    const int q0   = blockIdx.x * 128;
    const int g    = lane >> 2;
    const int t4   = lane & 3;

    const float slope = exp2f(-0.5f * (float)(h + 1));
    const float NEG_INF = -__int_as_float(0x7f800000);

    auto issue_kv = [&](int st, int kt2) {
        const int k0 = kt2 * 128;
        const __half* kh = Kh + ((size_t)bh * N_ + k0) * R_;
#pragma unroll
        for (int v = 0; v < 2; v++) {
            int idx = v * 256 + tid;      // 0..511
            int row = idx >> 2, q = idx & 3;
            cp16(sb + FK_BASE + st * FK_STAGE + (uint32_t)(row * 80 + q * 16),
                 kh + (size_t)row * R_ + q * 8);
        }
        const __half* vh = Vh + ((size_t)bh * N_ + k0) * DK_;
#pragma unroll
        for (int v = 0; v < 8; v++) {
            int idx = v * 256 + tid;      // 0..2047
            int row = idx >> 4, q = idx & 15;
            cp16(sb + FV_BASE + st * FV_STAGE + (uint32_t)(row * VSTR + q * 16),
                 vh + (size_t)row * DK_ + q * 8);
        }
    };

    // Q load (one-time, plain fp16)
    {
        const __half* qg = Qh + ((size_t)bh * N_ + q0) * R_;
#pragma unroll
        for (int v = 0; v < 2; v++) {
            int idx = v * 256 + tid;
            int row = idx >> 2, q = idx & 3;
            cp16(sb + FQ + (uint32_t)(row * 80 + q * 16),
                 qg + (size_t)row * R_ + q * 8);
        }
    }
    CP_COMMIT();
    issue_kv(0, 0); CP_COMMIT();
    issue_kv(1, 1); CP_COMMIT();

    CP_WAITG(2);
    __syncthreads();

    uint32_t qf[2][4];
    {
        uint32_t qaddr = sb + FQ +
            (uint32_t)((wq * 16 + (lane & 15)) * 80 + (lane >> 4) * 16);
#pragma unroll
        for (int ks = 0; ks < 2; ks++)
            ldsm_x4(qf[ks], qaddr + ks * 32);
    }

    float o[16][4];
#pragma unroll
    for (int d = 0; d < 16; d++)
#pragma unroll
        for (int f = 0; f < 4; f++) o[d][f] = 0.f;
    float m_i[2] = {NEG_INF, NEG_INF};
    float l_i[2] = {0.f, 0.f};

    for (int kt = 0; kt < N_ / 128; kt++) {
        const int k0 = kt * 128;
        CP_WAITG(1);
        __syncthreads();
        const int st = kt & 1;

        // ---- S = Q K^T (single-pass) ----
        float s[16][4];
#pragma unroll
        for (int nb = 0; nb < 16; nb++)
#pragma unroll
            for (int f = 0; f < 4; f++) s[nb][f] = 0.f;

        {
            uint32_t baddr = sb + FK_BASE + st * FK_STAGE +
                (uint32_t)((lane & 7) * 80 + ((lane >> 3) & 1) * 16);
#pragma unroll
            for (int ks = 0; ks < 2; ks++) {
#pragma unroll
                for (int nb = 0; nb < 16; nb++) {
                    uint32_t bhh[2];
                    ldsm_x2(bhh, baddr + (uint32_t)(nb * 640 + ks * 32));
                    mma_f16(s[nb], qf[ks], bhh);
                }
            }
        }

        // ---- ALiBi + online softmax (registers) ----
#pragma unroll
        for (int nb = 0; nb < 16; nb++) {
#pragma unroll
            for (int f = 0; f < 4; f++) {
                int r = f >> 1, c = f & 1;
                int jg = k0 + nb * 8 + t4 * 2 + c;
                int ig = q0 + wq * 16 + g + r * 8;
                s[nb][f] -= slope * fmaxf((float)(jg - ig), 0.f);
            }
        }

        float alpha[2], mnew[2];
#pragma unroll
        for (int r = 0; r < 2; r++) {
            float tm = NEG_INF;
#pragma unroll
            for (int nb = 0; nb < 16; nb++) {
                tm = fmaxf(tm, s[nb][r * 2]);
                tm = fmaxf(tm, s[nb][r * 2 + 1]);
            }
            tm = fmaxf(tm, __shfl_xor_sync(0xffffffffu, tm, 1));
            tm = fmaxf(tm, __shfl_xor_sync(0xffffffffu, tm, 2));
            mnew[r]  = fmaxf(m_i[r], tm);
            alpha[r] = __expf(m_i[r] - mnew[r]);
            m_i[r]   = mnew[r];
        }

        float rsum[2] = {0.f, 0.f};
#pragma unroll
        for (int nb = 0; nb < 16; nb++) {
#pragma unroll
            for (int f = 0; f < 4; f++) {
                int r = f >> 1;
                float p = __expf(s[nb][f] - mnew[r]);
                s[nb][f] = p;
                rsum[r] += p;
            }
        }
#pragma unroll
        for (int r = 0; r < 2; r++) {
            rsum[r] += __shfl_xor_sync(0xffffffffu, rsum[r], 1);
            rsum[r] += __shfl_xor_sync(0xffffffffu, rsum[r], 2);
            l_i[r] = l_i[r] * alpha[r] + rsum[r];
        }
#pragma unroll
        for (int d = 0; d < 16; d++)
#pragma unroll
            for (int f = 0; f < 4; f++) o[d][f] *= alpha[f >> 1];

        // ---- O += P V (single-pass) ----
        {
            uint32_t vaddr = sb + FV_BASE + st * FV_STAGE +
                (uint32_t)((lane & 15) * VSTR + (lane >> 4) * 16);
#pragma unroll
            for (int ks = 0; ks < 8; ks++) {
                uint32_t aP[4];
                aP[0] = packh2(s[2 * ks][0],     s[2 * ks][1]);
                aP[1] = packh2(s[2 * ks][2],     s[2 * ks][3]);
                aP[2] = packh2(s[2 * ks + 1][0], s[2 * ks + 1][1]);
                aP[3] = packh2(s[2 * ks + 1][2], s[2 * ks + 1][3]);
#pragma unroll
                for (int db = 0; db < 8; db++) {
                    uint32_t vh4[4];
                    ldsm_x4_t(vh4, vaddr + (uint32_t)(ks * 16 * VSTR + db * 32));
                    mma_f16(o[db * 2],     aP, vh4);
                    mma_f16(o[db * 2 + 1], aP, vh4 + 2);
                }
            }
        }
        __syncthreads();
        if (kt + 2 < N_ / 128) { issue_kv(st, kt + 2); CP_COMMIT(); }
    }

    // ---- finalize: Z (plain fp16) = O / l ----
    float inv[2] = {1.f / l_i[0], 1.f / l_i[1]};
#pragma unroll
    for (int db = 0; db < 16; db++) {
#pragma unroll
        for (int r = 0; r < 2; r++) {
            int row = q0 + wq * 16 + g + r * 8;
            size_t zoff = ((size_t)b_ * N_ + row) * D_ + h * DK_ + db * 8 + t4 * 2;
            *(uint32_t*)(Zh + zoff) =
                packh2(o[db][r * 2] * inv[r], o[db][r * 2 + 1] * inv[r]);
        }
    }
}

// ---------------------------------------------------------------------------
// Host launcher (graph-capturable: kernel launches only)
// ---------------------------------------------------------------------------
extern "C" void kernel_launch(void* const* d_in, const int* in_sizes, int n_in,
                              void* d_out, int out_size)
{
    (void)in_sizes; (void)n_in; (void)out_size;
    const float* x     = (const float*)d_in[0];
    const float* Wq    = (const float*)d_in[1];
    const float* Wk    = (const float*)d_in[2];
    const float* Wv    = (const float*)d_in[3];
    const float* U     = (const float*)d_in[4];
    const float* Wproj = (const float*)d_in[5];
    float* out = (float*)d_out;

    __half *xh, *WUqh, *WUkh, *Wvh, *Wph, *Qh, *Kh, *Vh, *Zh;
    cudaGetSymbolAddress((void**)&xh,   g_xh);
    cudaGetSymbolAddress((void**)&WUqh, g_WUqh);
    cudaGetSymbolAddress((void**)&WUkh, g_WUkh);
    cudaGetSymbolAddress((void**)&Wvh,  g_Wvh);
    cudaGetSymbolAddress((void**)&Wph,  g_Wph);
    cudaGetSymbolAddress((void**)&Qh,   g_Qh);
    cudaGetSymbolAddress((void**)&Kh,   g_Kh);
    cudaGetSymbolAddress((void**)&Vh,   g_Vh);
    cudaGetSymbolAddress((void**)&Zh,   g_Zh);

    cudaFuncSetAttribute(gemm_f16<2, R_>,
                         cudaFuncAttributeMaxDynamicSharedMemorySize, GEMM_SMEM);
    cudaFuncSetAttribute(gemm_f16<2, DK_>,
                         cudaFuncAttributeMaxDynamicSharedMemorySize, GEMM_SMEM);
    cudaFuncSetAttribute(gemm_f16<0, 1>,
                         cudaFuncAttributeMaxDynamicSharedMemorySize, GEMM_SMEM);
    cudaFuncSetAttribute(flash_f16_kernel,
                         cudaFuncAttributeMaxDynamicSharedMemorySize, FLM_SMEM);

    const float qscale = rsqrtf((float)DK_);

    // 0) one-time conversions + U-folding
    cvt_f16_kernel<<<(M_ * D_ / 4) / 256, 256>>>(
        (const float4*)x, (uint2*)xh, M_ * D_ / 4);
    cvt_f16_kernel<<<(D_ * D_ / 4) / 256, 256>>>(
        (const float4*)Wv, (uint2*)Wvh, D_ * D_ / 4);
    cvt_f16_kernel<<<(D_ * D_ / 4) / 256, 256>>>(
        (const float4*)Wproj, (uint2*)Wph, D_ * D_ / 4);
    build_wu_kernel<<<dim3(D_ / 256, H_, 4), 256>>>(Wq, U, WUqh);
    build_wu_kernel<<<dim3(D_ / 256, H_, 4), 256>>>(Wk, U, WUkh);

    // 1) Q = (x @ WUq^T) * 1/sqrt(dk) -> plain fp16 [b,h,n,r]
    gemm_f16<2, R_><<<dim3(HR_ / 128, M_ / 128), 256, GEMM_SMEM>>>(
        xh, WUqh, nullptr, Qh, HR_, D_, qscale);
    // 2) K = x @ WUk^T -> plain fp16
    gemm_f16<2, R_><<<dim3(HR_ / 128, M_ / 128), 256, GEMM_SMEM>>>(
        xh, WUkh, nullptr, Kh, HR_, D_, 1.0f);
    // 3) V = x @ Wv^T -> plain fp16 [b,h,n,dk]
    gemm_f16<2, DK_><<<dim3(D_ / 128, M_ / 128), 256, GEMM_SMEM>>>(
        xh, Wvh, nullptr, Vh, D_, D_, 1.0f);

    // 4) flash attention with ALiBi -> Z plain fp16 [b,n,d]
    flash_f16_kernel<<<dim3(N_ / 128, B_ * H_), 256, FLM_SMEM>>>(
        Qh, Kh, Vh, Zh);

    // 5) out = Z @ Wproj^T -> fp32
    gemm_f16<0, 1><<<dim3(D_ / 128, M_ / 128), 256, GEMM_SMEM>>>(
        Zh, Wph, out, nullptr, D_, D_, 1.0f);
}

// round 15
// speedup vs baseline: 2.4823x; 1.0187x over previous
#include <cuda_runtime.h>
#include <cuda_fp16.h>
#include <math.h>
#include <stdint.h>

// ---------------------------------------------------------------------------
// Problem constants (B=4, N=2048, D=2048, H=16, DK=128, R=32)
// ---------------------------------------------------------------------------
#define B_   4
#define N_   2048
#define D_   2048
#define H_   16
#define DK_  128
#define R_   32
#define M_   (B_ * N_)      // 8192
#define HR_  (H_ * R_)      // 512

// ---------------------------------------------------------------------------
// Device scratch (all plain fp16)
// ---------------------------------------------------------------------------
__device__ __half g_xh  [(size_t)M_ * D_];
__device__ __half g_WUqh[(size_t)HR_ * D_];
__device__ __half g_WUkh[(size_t)HR_ * D_];
__device__ __half g_Wvh [(size_t)D_ * D_];
__device__ __half g_Wph [(size_t)D_ * D_];
__device__ __half g_Qh  [(size_t)B_ * H_ * N_ * R_];
__device__ __half g_Kh  [(size_t)B_ * H_ * N_ * R_];
__device__ __half g_Vh  [(size_t)B_ * H_ * N_ * DK_];
__device__ __half g_Zh  [(size_t)M_ * D_];

// ---------------------------------------------------------------------------
// PTX wrappers (sm_80-era, valid on plain sm_103 target)
// ---------------------------------------------------------------------------
__device__ __forceinline__ uint32_t smem_u32(const void* p) {
    uint32_t a;
    asm("{ .reg .u64 t; cvta.to.shared.u64 t, %1; cvt.u32.u64 %0, t; }"
        : "=r"(a) : "l"(p));
    return a;
}
__device__ __forceinline__ void ldsm_x4(uint32_t* r, uint32_t addr) {
    asm volatile("ldmatrix.sync.aligned.m8n8.x4.shared.b16 {%0,%1,%2,%3}, [%4];"
                 : "=r"(r[0]), "=r"(r[1]), "=r"(r[2]), "=r"(r[3]) : "r"(addr));
}
__device__ __forceinline__ void ldsm_x2(uint32_t* r, uint32_t addr) {
    asm volatile("ldmatrix.sync.aligned.m8n8.x2.shared.b16 {%0,%1}, [%2];"
                 : "=r"(r[0]), "=r"(r[1]) : "r"(addr));
}
__device__ __forceinline__ void ldsm_x4_t(uint32_t* r, uint32_t addr) {
    asm volatile("ldmatrix.sync.aligned.m8n8.x4.trans.shared.b16 {%0,%1,%2,%3}, [%4];"
                 : "=r"(r[0]), "=r"(r[1]), "=r"(r[2]), "=r"(r[3]) : "r"(addr));
}
__device__ __forceinline__ void mma_f16(float* d, const uint32_t* a, const uint32_t* b) {
    asm volatile(
        "mma.sync.aligned.m16n8k16.row.col.f32.f16.f16.f32 "
        "{%0,%1,%2,%3}, {%4,%5,%6,%7}, {%8,%9}, {%0,%1,%2,%3};"
        : "+f"(d[0]), "+f"(d[1]), "+f"(d[2]), "+f"(d[3])
        : "r"(a[0]), "r"(a[1]), "r"(a[2]), "r"(a[3]), "r"(b[0]), "r"(b[1]));
}
__device__ __forceinline__ void cp16(uint32_t dst, const void* src) {
    asm volatile("cp.async.cg.shared.global [%0], [%1], 16;"
                 :: "r"(dst), "l"(src) : "memory");
}
#define CP_COMMIT() asm volatile("cp.async.commit_group;" ::: "memory")
#define CP_WAITG(n) asm volatile("cp.async.wait_group %0;" :: "n"(n) : "memory")

__device__ __forceinline__ uint32_t packh2(float x, float y) {
    __half2 hh = __floats2half2_rn(x, y);
    return *reinterpret_cast<uint32_t*>(&hh);
}

// ---------------------------------------------------------------------------
// Prep kernels (fused)
// ---------------------------------------------------------------------------
// One launch converts x, Wv, Wproj. Ranges in units of float4.
__global__ void cvt3_f16_kernel(const float4* __restrict__ s0, uint2* __restrict__ d0, int n0,
                                const float4* __restrict__ s1, uint2* __restrict__ d1, int n1,
                                const float4* __restrict__ s2, uint2* __restrict__ d2, int n2)
{
    int i = blockIdx.x * 256 + threadIdx.x;
    const float4* s; uint2* d;
    if (i < n0)           { s = s0;       d = d0;       }
    else if (i < n0 + n1) { s = s1;       d = d1;       i -= n0;      }
    else if (i < n0 + n1 + n2) { s = s2;  d = d2;       i -= n0 + n1; }
    else return;
    float4 v = s[i];
    d[i] = make_uint2(packh2(v.x, v.y), packh2(v.z, v.w));
}

// Fused WUq/WUk: z in 0..7; z<4 -> (Wq, WUq, rg=z), else (Wk, WUk, rg=z-4)
__global__ void build_wu_kernel(const float* __restrict__ Wq,
                                const float* __restrict__ Wk,
                                const float* __restrict__ U,
                                __half* __restrict__ WUq_,
                                __half* __restrict__ WUk_)
{
    __shared__ float Us[128][8];
    const int tid = threadIdx.x;
    const int d   = blockIdx.x * 256 + tid;
    const int h   = blockIdx.y;
    const int z   = blockIdx.z;
    const int rg  = z & 3;
    const float* W   = (z < 4) ? Wq : Wk;
    __half* WUh      = (z < 4) ? WUq_ : WUk_;

    for (int i = tid; i < 128 * 8; i += 256) {
        int dk = i >> 3, j = i & 7;
        Us[dk][j] = U[dk * R_ + rg * 8 + j];
    }
    __syncthreads();

    const float* wcol = W + (size_t)h * DK_ * D_ + d;
    float acc[8];
#pragma unroll
    for (int j = 0; j < 8; j++) acc[j] = 0.f;
#pragma unroll 4
    for (int dk = 0; dk < DK_; dk++) {
        float w = wcol[(size_t)dk * D_];
#pragma unroll
        for (int j = 0; j < 8; j++) acc[j] = fmaf(w, Us[dk][j], acc[j]);
    }
#pragma unroll
    for (int j = 0; j < 8; j++) {
        size_t off = (size_t)(h * 32 + rg * 8 + j) * D_ + d;
        WUh[off] = __float2half(acc[j]);
    }
}

// ---------------------------------------------------------------------------
// HMMA fp16 GEMM (single-pass; unchanged from R14 — proven at the HMMA floor)
// ---------------------------------------------------------------------------
#define SGS 20480u
#define GEMM_SMEM (2 * 20480)

template <int MODE, int SPLIT>
__global__ void __launch_bounds__(256, 2)
gemm_f16(const __half* __restrict__ A_,
         const __half* __restrict__ B_x,
         float* __restrict__ Cf,
         __half* __restrict__ Ch,
         int NN, int K, float scale)
{
    extern __shared__ char sm[];
    const uint32_t sb = smem_u32(sm);

    const int tid  = threadIdx.x;
    const int lane = tid & 31;
    const int wid  = tid >> 5;
    const int wm   = wid & 1;
    const int wn   = wid >> 1;
    const int m0   = blockIdx.y * 128;
    const int n0   = blockIdx.x * 128;

    const __half* bases[2] = { A_ + (size_t)m0 * K, B_x + (size_t)n0 * K };

    auto issue = [&](int st, int it) {
        const uint32_t stb = sb + (uint32_t)st * SGS;
#pragma unroll
        for (int v = 0; v < 4; v++) {
            const int p = v >> 1;
            int rq = (v & 1) * 256 + tid;
            int r  = rq >> 2, q = rq & 3;
            const __half* src = bases[p] + (size_t)r * K + it * 32 + q * 8;
            cp16(stb + (uint32_t)(p * 10240 + r * 80 + q * 16), src);
        }
    };

    const int niter = K / 32;
    issue(0, 0); CP_COMMIT();
    issue(1, 1); CP_COMMIT();

    float acc[4][4][4];
#pragma unroll
    for (int mi = 0; mi < 4; mi++)
#pragma unroll
        for (int ni = 0; ni < 4; ni++)
#pragma unroll
            for (int f = 0; f < 4; f++) acc[mi][ni][f] = 0.f;

    const uint32_t a_off =
        (uint32_t)((wm * 64 + (lane & 15)) * 80 + (lane >> 4) * 16);
    const uint32_t b_off = 10240u +
        (uint32_t)((wn * 32 + (lane & 7)) * 80 + ((lane >> 3) & 1) * 16);

    for (int it = 0; it < niter; ++it) {
        CP_WAITG(1);
        __syncthreads();
        const uint32_t stb = sb + (uint32_t)(it & 1) * SGS;
        const uint32_t a_addr = stb + a_off;
        const uint32_t b_addr = stb + b_off;

#pragma unroll
        for (int ks = 0; ks < 2; ks++) {
            uint32_t ah[4][4];
#pragma unroll
            for (int mi = 0; mi < 4; mi++)
                ldsm_x4(ah[mi], a_addr + (uint32_t)(mi * 1280 + ks * 32));
#pragma unroll
            for (int ni = 0; ni < 4; ni++) {
                uint32_t bh[2];
                ldsm_x2(bh, b_addr + (uint32_t)(ni * 640 + ks * 32));
#pragma unroll
                for (int mi = 0; mi < 4; mi++)
                    mma_f16(acc[mi][ni], ah[mi], bh);
            }
        }
        __syncthreads();
        if (it + 2 < niter) { issue(it & 1, it + 2); CP_COMMIT(); }
    }

    const int g  = lane >> 2;
    const int c2 = (lane & 3) * 2;
#pragma unroll
    for (int mi = 0; mi < 4; mi++) {
#pragma unroll
        for (int ni = 0; ni < 4; ni++) {
            int m = m0 + wm * 64 + mi * 16 + g;
            int n = n0 + wn * 32 + ni * 8 + c2;
#pragma unroll
            for (int half_ = 0; half_ < 2; half_++) {
                int mm = m + half_ * 8;
                float v0 = acc[mi][ni][half_ * 2];
                float v1 = acc[mi][ni][half_ * 2 + 1];
                if (MODE == 0) {
                    *(float2*)(Cf + (size_t)mm * NN + n) = make_float2(v0, v1);
                } else {
                    int b_ = mm >> 11;
                    int t  = mm & (N_ - 1);
                    int h  = n / SPLIT;
                    int j  = n % SPLIT;
                    size_t off = (((size_t)(b_ * H_ + h)) * N_ + t) * SPLIT + j;
                    *(uint32_t*)(Ch + off) = packh2(v0 * scale, v1 * scale);
                }
            }
        }
    }
}

// ---------------------------------------------------------------------------
// HMMA flash attention v2: 128 threads (4 warps), 64 q-rows per CTA,
// 2 CTAs/SM so one CTA's HMMAs cover the other's softmax phase.
// smem: Q 5120 | K stages 2x10240 | V stages 2x34816 = 95232 B
// ---------------------------------------------------------------------------
#define FQ 0
#define FK_BASE 5120
#define FK_STAGE 10240
#define FV_BASE 25600
#define FV_STAGE 34816
#define FLM_SMEM 95232
#define VSTR 272

__global__ void __launch_bounds__(128, 2)
flash_f16_kernel(const __half* __restrict__ Qh,
                 const __half* __restrict__ Kh,
                 const __half* __restrict__ Vh,
                 __half* __restrict__ Zh)
{
    extern __shared__ char sm[];
    const uint32_t sb = smem_u32(sm);

    const int tid  = threadIdx.x;
    const int lane = tid & 31;
    const int wq   = tid >> 5;            // 0..3 -> q rows wq*16..+15
    const int bh   = blockIdx.y;
    const int h    = bh & (H_ - 1);
    const int b_   = bh >> 4;
    const int q0   = blockIdx.x * 64;
    const int g    = lane >> 2;
    const int t4   = lane & 3;

    const float slope = exp2f(-0.5f * (float)(h + 1));
    const float NEG_INF = -__int_as_float(0x7f800000);

    auto issue_kv = [&](int st, int kt2) {
        const int k0 = kt2 * 128;
        const __half* kh = Kh + ((size_t)bh * N_ + k0) * R_;
#pragma unroll
        for (int v = 0; v < 4; v++) {
            int idx = v * 128 + tid;      // 0..511
            int row = idx >> 2, q = idx & 3;
            cp16(sb + FK_BASE + st * FK_STAGE + (uint32_t)(row * 80 + q * 16),
                 kh + (size_t)row * R_ + q * 8);
        }
        const __half* vh = Vh + ((size_t)bh * N_ + k0) * DK_;
#pragma unroll
        for (int v = 0; v < 16; v++) {
            int idx = v * 128 + tid;      // 0..2047
            int row = idx >> 4, q = idx & 15;
            cp16(sb + FV_BASE + st * FV_STAGE + (uint32_t)(row * VSTR + q * 16),
                 vh + (size_t)row * DK_ + q * 8);
        }
    };

    // Q load (one-time, 64 rows x 32 cols fp16 = 256 chunks)
    {
        const __half* qg = Qh + ((size_t)bh * N_ + q0) * R_;
#pragma unroll
        for (int v = 0; v < 2; v++) {
            int idx = v * 128 + tid;
            int row = idx >> 2, q = idx & 3;
            cp16(sb + FQ + (uint32_t)(row * 80 + q * 16),
                 qg + (size_t)row * R_ + q * 8);
        }
    }
    CP_COMMIT();
    issue_kv(0, 0); CP_COMMIT();
    issue_kv(1, 1); CP_COMMIT();

    CP_WAITG(2);
    __syncthreads();

    uint32_t qf[2][4];
    {
        uint32_t qaddr = sb + FQ +
            (uint32_t)((wq * 16 + (lane & 15)) * 80 + (lane >> 4) * 16);
#pragma unroll
        for (int ks = 0; ks < 2; ks++)
            ldsm_x4(qf[ks], qaddr + ks * 32);
    }

    float o[16][4];
#pragma unroll
    for (int d = 0; d < 16; d++)
#pragma unroll
        for (int f = 0; f < 4; f++) o[d][f] = 0.f;
    float m_i[2] = {NEG_INF, NEG_INF};
    float l_i[2] = {0.f, 0.f};

    for (int kt = 0; kt < N_ / 128; kt++) {
        const int k0 = kt * 128;
        CP_WAITG(1);
        __syncthreads();
        const int st = kt & 1;

        // ---- S = Q K^T ----
        float s[16][4];
#pragma unroll
        for (int nb = 0; nb < 16; nb++)
#pragma unroll
            for (int f = 0; f < 4; f++) s[nb][f] = 0.f;

        {
            uint32_t baddr = sb + FK_BASE + st * FK_STAGE +
                (uint32_t)((lane & 7) * 80 + ((lane >> 3) & 1) * 16);
#pragma unroll
            for (int ks = 0; ks < 2; ks++) {
#pragma unroll
                for (int nb = 0; nb < 16; nb++) {
                    uint32_t bhh[2];
                    ldsm_x2(bhh, baddr + (uint32_t)(nb * 640 + ks * 32));
                    mma_f16(s[nb], qf[ks], bhh);
                }
            }
        }

        // ---- ALiBi + online softmax (registers) ----
#pragma unroll
        for (int nb = 0; nb < 16; nb++) {
#pragma unroll
            for (int f = 0; f < 4; f++) {
                int r = f >> 1, c = f & 1;
                int jg = k0 + nb * 8 + t4 * 2 + c;
                int ig = q0 + wq * 16 + g + r * 8;
                s[nb][f] -= slope * fmaxf((float)(jg - ig), 0.f);
            }
        }

        float alpha[2], mnew[2];
#pragma unroll
        for (int r = 0; r < 2; r++) {
            float tm = NEG_INF;
#pragma unroll
            for (int nb = 0; nb < 16; nb++) {
                tm = fmaxf(tm, s[nb][r * 2]);
                tm = fmaxf(tm, s[nb][r * 2 + 1]);
            }
            tm = fmaxf(tm, __shfl_xor_sync(0xffffffffu, tm, 1));
            tm = fmaxf(tm, __shfl_xor_sync(0xffffffffu, tm, 2));
            mnew[r]  = fmaxf(m_i[r], tm);
            alpha[r] = __expf(m_i[r] - mnew[r]);
            m_i[r]   = mnew[r];
        }

        float rsum[2] = {0.f, 0.f};
#pragma unroll
        for (int nb = 0; nb < 16; nb++) {
#pragma unroll
            for (int f = 0; f < 4; f++) {
                int r = f >> 1;
                float p = __expf(s[nb][f] - mnew[r]);
                s[nb][f] = p;
                rsum[r] += p;
            }
        }
#pragma unroll
        for (int r = 0; r < 2; r++) {
            rsum[r] += __shfl_xor_sync(0xffffffffu, rsum[r], 1);
            rsum[r] += __shfl_xor_sync(0xffffffffu, rsum[r], 2);
            l_i[r] = l_i[r] * alpha[r] + rsum[r];
        }
#pragma unroll
        for (int d = 0; d < 16; d++)
#pragma unroll
            for (int f = 0; f < 4; f++) o[d][f] *= alpha[f >> 1];

        // ---- O += P V ----
        {
            uint32_t vaddr = sb + FV_BASE + st * FV_STAGE +
                (uint32_t)((lane & 15) * VSTR + (lane >> 4) * 16);
#pragma unroll
            for (int ks = 0; ks < 8; ks++) {
                uint32_t aP[4];
                aP[0] = packh2(s[2 * ks][0],     s[2 * ks][1]);
                aP[1] = packh2(s[2 * ks][2],     s[2 * ks][3]);
                aP[2] = packh2(s[2 * ks + 1][0], s[2 * ks + 1][1]);
                aP[3] = packh2(s[2 * ks + 1][2], s[2 * ks + 1][3]);
#pragma unroll
                for (int db = 0; db < 8; db++) {
                    uint32_t vh4[4];
                    ldsm_x4_t(vh4, vaddr + (uint32_t)(ks * 16 * VSTR + db * 32));
                    mma_f16(o[db * 2],     aP, vh4);
                    mma_f16(o[db * 2 + 1], aP, vh4 + 2);
                }
            }
        }
        __syncthreads();
        if (kt + 2 < N_ / 128) { issue_kv(st, kt + 2); CP_COMMIT(); }
    }

    // ---- finalize: Z (plain fp16) = O / l ----
    float inv[2] = {1.f / l_i[0], 1.f / l_i[1]};
#pragma unroll
    for (int db = 0; db < 16; db++) {
#pragma unroll
        for (int r = 0; r < 2; r++) {
            int row = q0 + wq * 16 + g + r * 8;
            size_t zoff = ((size_t)b_ * N_ + row) * D_ + h * DK_ + db * 8 + t4 * 2;
            *(uint32_t*)(Zh + zoff) =
                packh2(o[db][r * 2] * inv[r], o[db][r * 2 + 1] * inv[r]);
        }
    }
}

// ---------------------------------------------------------------------------
// Host launcher (graph-capturable: kernel launches only)
// ---------------------------------------------------------------------------
extern "C" void kernel_launch(void* const* d_in, const int* in_sizes, int n_in,
                              void* d_out, int out_size)
{
    (void)in_sizes; (void)n_in; (void)out_size;
    const float* x     = (const float*)d_in[0];
    const float* Wq    = (const float*)d_in[1];
    const float* Wk    = (const float*)d_in[2];
    const float* Wv    = (const float*)d_in[3];
    const float* U     = (const float*)d_in[4];
    const float* Wproj = (const float*)d_in[5];
    float* out = (float*)d_out;

    __half *xh, *WUqh, *WUkh, *Wvh, *Wph, *Qh, *Kh, *Vh, *Zh;
    cudaGetSymbolAddress((void**)&xh,   g_xh);
    cudaGetSymbolAddress((void**)&WUqh, g_WUqh);
    cudaGetSymbolAddress((void**)&WUkh, g_WUkh);
    cudaGetSymbolAddress((void**)&Wvh,  g_Wvh);
    cudaGetSymbolAddress((void**)&Wph,  g_Wph);
    cudaGetSymbolAddress((void**)&Qh,   g_Qh);
    cudaGetSymbolAddress((void**)&Kh,   g_Kh);
    cudaGetSymbolAddress((void**)&Vh,   g_Vh);
    cudaGetSymbolAddress((void**)&Zh,   g_Zh);

    cudaFuncSetAttribute(gemm_f16<2, R_>,
                         cudaFuncAttributeMaxDynamicSharedMemorySize, GEMM_SMEM);
    cudaFuncSetAttribute(gemm_f16<2, DK_>,
                         cudaFuncAttributeMaxDynamicSharedMemorySize, GEMM_SMEM);
    cudaFuncSetAttribute(gemm_f16<0, 1>,
                         cudaFuncAttributeMaxDynamicSharedMemorySize, GEMM_SMEM);
    cudaFuncSetAttribute(flash_f16_kernel,
                         cudaFuncAttributeMaxDynamicSharedMemorySize, FLM_SMEM);

    const float qscale = rsqrtf((float)DK_);

    // 0) fused conversions + fused U-folding
    {
        const int n0 = M_ * D_ / 4, n1 = D_ * D_ / 4, n2 = D_ * D_ / 4;
        const int total = n0 + n1 + n2;
        cvt3_f16_kernel<<<(total + 255) / 256, 256>>>(
            (const float4*)x,     (uint2*)xh,  n0,
            (const float4*)Wv,    (uint2*)Wvh, n1,
            (const float4*)Wproj, (uint2*)Wph, n2);
    }
    build_wu_kernel<<<dim3(D_ / 256, H_, 8), 256>>>(Wq, Wk, U, WUqh, WUkh);

    // 1) Q = (x @ WUq^T) * 1/sqrt(dk) -> plain fp16 [b,h,n,r]
    gemm_f16<2, R_><<<dim3(HR_ / 128, M_ / 128), 256, GEMM_SMEM>>>(
        xh, WUqh, nullptr, Qh, HR_, D_, qscale);
    // 2) K = x @ WUk^T -> plain fp16
    gemm_f16<2, R_><<<dim3(HR_ / 128, M_ / 128), 256, GEMM_SMEM>>>(
        xh, WUkh, nullptr, Kh, HR_, D_, 1.0f);
    // 3) V = x @ Wv^T -> plain fp16 [b,h,n,dk]
    gemm_f16<2, DK_><<<dim3(D_ / 128, M_ / 128), 256, GEMM_SMEM>>>(
        xh, Wvh, nullptr, Vh, D_, D_, 1.0f);

    // 4) flash attention with ALiBi -> Z plain fp16 [b,n,d]
    //    grid: q-tile fast-varying so same-bh CTAs are co-resident (L2 reuse)
    flash_f16_kernel<<<dim3(N_ / 64, B_ * H_), 128, FLM_SMEM>>>(
        Qh, Kh, Vh, Zh);

    // 5) out = Z @ Wproj^T -> fp32
    gemm_f16<0, 1><<<dim3(D_ / 128, M_ / 128), 256, GEMM_SMEM>>>(
        Zh, Wph, out, nullptr, D_, D_, 1.0f);
}